// round 8
// baseline (speedup 1.0000x reference)
#include <cuda_runtime.h>
#include <math.h>
#include <stdint.h>

#define Dd  512
#define Hh  8
#define HD  64
#define Bb  2
#define Ss  256
#define Ff  2048
#define Cc  4
#define Vv  32000
#define TOK (Bb*Ss)   // 512

// ---------------- device state (no allocation allowed) ----------------
__device__ float g_x [TOK*Dd];
__device__ float g_xn[TOK*Dd];
__device__ float g_q [TOK*Dd];
__device__ float g_k [TOK*Dd];
__device__ float g_v [TOK*Dd];
__device__ float g_o [TOK*Dd];
__device__ float g_ff[TOK*Ff];
__device__ float g_part[12*TOK*Dd];   // also holds 2x TOK*Ff for W1
__device__ float g_pool[Bb*Dd];
__device__ int   g_cur[Bb];
__device__ float g_accp[Cc+1];
__device__ float g_acclb;

// ---------------- init ----------------
__global__ void init_k(const int* __restrict__ start) {
    if (threadIdx.x == 0) {
        g_cur[0] = start[0];
        g_cur[1] = start[1];
        #pragma unroll
        for (int i = 0; i < Cc+1; i++) g_accp[i] = 0.f;
        g_acclb = 0.f;
    }
}

// ---------------- embedding ----------------
__global__ void embed_k(const int* __restrict__ ids, const float* __restrict__ emb,
                        float* __restrict__ x) {
    int t = blockIdx.x;
    int d = threadIdx.x;
    float scale = sqrtf((float)Dd);
    x[t*Dd + d] = emb[(size_t)ids[t]*Dd + d] * scale;
}

// ---------------- rmsnorm (block per token) ----------------
__global__ void rmsnorm_k(const float* __restrict__ x, const float* __restrict__ w,
                          const int* __restrict__ cur, float* __restrict__ out) {
    int t = blockIdx.x;
    int d = threadIdx.x;          // 512
    __shared__ float red[512];
    float v = x[t*Dd + d];
    red[d] = v*v;
    __syncthreads();
    for (int s = 256; s > 0; s >>= 1) {
        if (d < s) red[d] += red[d+s];
        __syncthreads();
    }
    float scale = rsqrtf(red[0] * (1.0f/Dd) + 1e-6f);
    const float* ww = w;
    if (cur) ww += (size_t)cur[t / Ss] * Dd;
    out[t*Dd + d] = v * scale * ww[d];
}

// ---------------- tf32 / cp.async helpers ----------------
__device__ __forceinline__ uint32_t f2tf32(float f) {
    uint32_t u;
    asm volatile("cvt.rna.tf32.f32 %0, %1;" : "=r"(u) : "f"(f));
    return u;
}

__device__ __forceinline__ void mma_tf32(float c[4],
    uint32_t a0, uint32_t a1, uint32_t a2, uint32_t a3,
    uint32_t b0, uint32_t b1)
{
    asm volatile(
        "mma.sync.aligned.m16n8k8.row.col.f32.tf32.tf32.f32 "
        "{%0,%1,%2,%3}, {%4,%5,%6,%7}, {%8,%9}, {%0,%1,%2,%3};"
        : "+f"(c[0]), "+f"(c[1]), "+f"(c[2]), "+f"(c[3])
        : "r"(a0), "r"(a1), "r"(a2), "r"(a3), "r"(b0), "r"(b1));
}

__device__ __forceinline__ void cp_async16(float* smem, const float* gmem) {
    uint32_t s;
    asm("{ .reg .u64 t; cvta.to.shared.u64 t, %1; cvt.u32.u64 %0, t; }"
        : "=r"(s) : "l"(smem));
    asm volatile("cp.async.cg.shared.global [%0], [%1], 16;" :: "r"(s), "l"(gmem) : "memory");
}
#define CP_COMMIT()  asm volatile("cp.async.commit_group;" ::: "memory")
#define CP_WAIT1()   asm volatile("cp.async.wait_group 1;" ::: "memory")
#define CP_WAIT0()   asm volatile("cp.async.wait_group 0;" ::: "memory")

// ---------------- tensor-core logits GEMM (verified) ------
#define TC_SMEM ((2*128*36 + 2*32*136) * (int)sizeof(float))
__global__ void __launch_bounds__(256,2) gemm_tc(
    const float* __restrict__ A, const float* __restrict__ W,
    float* __restrict__ Out, int K, int N)
{
    extern __shared__ float dsm[];
    float (*As)[128][36]  = (float(*)[128][36])dsm;
    float (*Bs)[32][136]  = (float(*)[32][136])(dsm + 2*128*36);
    int tid = threadIdx.x;
    int m0 = blockIdx.x*128, n0 = blockIdx.y*128;
    int warp = tid >> 5, lane = tid & 31;
    int wm = warp & 1, wn = warp >> 1;
    int g = lane >> 2, tg = lane & 3;

    auto issue = [&](int k0, int buf) {
        #pragma unroll
        for (int l = 0; l < 4; l++) {
            int idx = tid + l*256;
            int row = idx >> 3, kc = (idx & 7) * 4;
            cp_async16(&As[buf][row][kc], &A[(size_t)(m0+row)*K + k0 + kc]);
        }
        #pragma unroll
        for (int l = 0; l < 4; l++) {
            int idx = tid + l*256;
            int kr = idx >> 5, nc = (idx & 31) * 4;
            cp_async16(&Bs[buf][kr][nc], &W[(size_t)(k0+kr)*N + n0 + nc]);
        }
        CP_COMMIT();
    };

    float acc[4][4][4] = {};
    int nk = K / 32;
    issue(0, 0);
    int buf = 0;
    for (int it = 0; it < nk; it++) {
        bool more = (it + 1) < nk;
        if (more) issue((it+1)*32, buf^1);
        if (more) CP_WAIT1(); else CP_WAIT0();
        __syncthreads();

        #pragma unroll
        for (int kk = 0; kk < 32; kk += 8) {
            uint32_t af[4][4], bf[4][2];
            #pragma unroll
            for (int mt = 0; mt < 4; mt++) {
                int mrow = wm*64 + mt*16 + g;
                af[mt][0] = f2tf32(As[buf][mrow  ][kk+tg]);
                af[mt][1] = f2tf32(As[buf][mrow+8][kk+tg]);
                af[mt][2] = f2tf32(As[buf][mrow  ][kk+tg+4]);
                af[mt][3] = f2tf32(As[buf][mrow+8][kk+tg+4]);
            }
            #pragma unroll
            for (int nt = 0; nt < 4; nt++) {
                int ncol = wn*32 + nt*8 + g;
                bf[nt][0] = f2tf32(Bs[buf][kk+tg  ][ncol]);
                bf[nt][1] = f2tf32(Bs[buf][kk+tg+4][ncol]);
            }
            #pragma unroll
            for (int mt = 0; mt < 4; mt++)
                #pragma unroll
                for (int nt = 0; nt < 4; nt++)
                    mma_tf32(acc[mt][nt], af[mt][0], af[mt][1], af[mt][2], af[mt][3],
                             bf[nt][0], bf[nt][1]);
        }
        __syncthreads();
        buf ^= 1;
    }

    #pragma unroll
    for (int mt = 0; mt < 4; mt++) {
        #pragma unroll
        for (int nt = 0; nt < 4; nt++) {
            int row = m0 + wm*64 + mt*16 + g;
            int col = n0 + wn*32 + nt*8 + 2*tg;
            float2 lo = { acc[mt][nt][0], acc[mt][nt][1] };
            float2 hi = { acc[mt][nt][2], acc[mt][nt][3] };
            *(float2*)&Out[(size_t)row*N + col]     = lo;
            *(float2*)&Out[(size_t)(row+8)*N + col] = hi;
        }
    }
}

// ---------------- tf32x3 mid GEMM core (verified) ----------------
__device__ __forceinline__ void tc64_core(
    const float* __restrict__ A, int lda, const float* __restrict__ W,
    int K, int N, int m0, int n0, int tid, float acc[2][2][4])
{
    __shared__ float As[2][64][36];
    __shared__ float Bs[2][32][72];
    int warp = tid >> 5, lane = tid & 31;
    int wm = warp & 1, wn = warp >> 1;
    int g = lane >> 2, tg = lane & 3;

    auto issue = [&](int k0, int buf) {
        #pragma unroll
        for (int l = 0; l < 2; l++) {
            int idx = tid + l*256;
            int row = idx >> 3, kc = (idx & 7) * 4;
            cp_async16(&As[buf][row][kc], &A[(size_t)(m0+row)*lda + k0 + kc]);
        }
        #pragma unroll
        for (int l = 0; l < 2; l++) {
            int idx = tid + l*256;
            int kr = idx >> 4, nc = (idx & 15) * 4;
            cp_async16(&Bs[buf][kr][nc], &W[(size_t)(k0+kr)*N + n0 + nc]);
        }
        CP_COMMIT();
    };

    int nk = K / 32;
    issue(0, 0);
    int buf = 0;
    for (int it = 0; it < nk; it++) {
        bool more = (it + 1) < nk;
        if (more) issue((it+1)*32, buf^1);
        if (more) CP_WAIT1(); else CP_WAIT0();
        __syncthreads();

        #pragma unroll
        for (int kk = 0; kk < 32; kk += 8) {
            uint32_t ah[2][4], al[2][4], bh[2][2], bl[2][2];
            #pragma unroll
            for (int mt = 0; mt < 2; mt++) {
                int mrow = wm*32 + mt*16 + g;
                float a0 = As[buf][mrow  ][kk+tg];
                float a1 = As[buf][mrow+8][kk+tg];
                float a2 = As[buf][mrow  ][kk+tg+4];
                float a3 = As[buf][mrow+8][kk+tg+4];
                ah[mt][0] = f2tf32(a0); al[mt][0] = f2tf32(a0 - __uint_as_float(ah[mt][0]));
                ah[mt][1] = f2tf32(a1); al[mt][1] = f2tf32(a1 - __uint_as_float(ah[mt][1]));
                ah[mt][2] = f2tf32(a2); al[mt][2] = f2tf32(a2 - __uint_as_float(ah[mt][2]));
                ah[mt][3] = f2tf32(a3); al[mt][3] = f2tf32(a3 - __uint_as_float(ah[mt][3]));
            }
            #pragma unroll
            for (int nt = 0; nt < 2; nt++) {
                int ncol = wn*16 + nt*8 + g;
                float b0 = Bs[buf][kk+tg  ][ncol];
                float b1 = Bs[buf][kk+tg+4][ncol];
                bh[nt][0] = f2tf32(b0); bl[nt][0] = f2tf32(b0 - __uint_as_float(bh[nt][0]));
                bh[nt][1] = f2tf32(b1); bl[nt][1] = f2tf32(b1 - __uint_as_float(bh[nt][1]));
            }
            #pragma unroll
            for (int mt = 0; mt < 2; mt++)
                #pragma unroll
                for (int nt = 0; nt < 2; nt++) {
                    mma_tf32(acc[mt][nt], ah[mt][0], ah[mt][1], ah[mt][2], ah[mt][3],
                             bl[nt][0], bl[nt][1]);
                    mma_tf32(acc[mt][nt], al[mt][0], al[mt][1], al[mt][2], al[mt][3],
                             bh[nt][0], bh[nt][1]);
                    mma_tf32(acc[mt][nt], ah[mt][0], ah[mt][1], ah[mt][2], ah[mt][3],
                             bh[nt][0], bh[nt][1]);
                }
        }
        __syncthreads();
        buf ^= 1;
    }
}

__device__ __forceinline__ void tc64_store(
    float acc[2][2][4], float* __restrict__ Out, int N, int m0, int n0, int tid)
{
    int warp = tid >> 5, lane = tid & 31;
    int wm = warp & 1, wn = warp >> 1;
    int g = lane >> 2, tg = lane & 3;
    #pragma unroll
    for (int mt = 0; mt < 2; mt++) {
        #pragma unroll
        for (int nt = 0; nt < 2; nt++) {
            int row = m0 + wm*32 + mt*16 + g;
            int col = n0 + wn*16 + nt*8 + 2*tg;
            float2 lo = { acc[mt][nt][0], acc[mt][nt][1] };
            float2 hi = { acc[mt][nt][2], acc[mt][nt][3] };
            *(float2*)&Out[(size_t)row*N + col]     = lo;
            *(float2*)&Out[(size_t)(row+8)*N + col] = hi;
        }
    }
}

// ---------------- generic split-K mid GEMM -> partials ----------------
// grid.z = split idx; A row stride lda=Kfull; partial z at part + z*TOK*N
__global__ void __launch_bounds__(256) gemm_sk(
    const float* __restrict__ A, const float* __restrict__ Wb,
    float* __restrict__ part, const int* __restrict__ cur,
    int Kfull, int klen, int N)
{
    int m0 = blockIdx.y*64, n0 = blockIdx.x*64;
    int z = blockIdx.z;
    const float* W = Wb + (size_t)cur[m0 / Ss] * Kfull * N + (size_t)z * klen * N;
    float acc[2][2][4] = {};
    tc64_core(A + (size_t)z * klen, Kfull, W, klen, N, m0, n0, threadIdx.x, acc);
    tc64_store(acc, part + (size_t)z * TOK * N, N, m0, n0, threadIdx.x);
}

// ---------------- split-K QKV -> 12 partials (op*4 + quarter) ----------------
__global__ void __launch_bounds__(256) qkv_sk(
    const float* __restrict__ xn,
    const float* __restrict__ Wq, const float* __restrict__ Wk, const float* __restrict__ Wv,
    float* __restrict__ part, const int* __restrict__ cur)
{
    int z = blockIdx.z;
    int op = z >> 2, qtr = z & 3;
    const float* Wb = (op == 0) ? Wq : (op == 1) ? Wk : Wv;
    int m0 = blockIdx.y*64, n0 = blockIdx.x*64;
    const float* W = Wb + (size_t)cur[m0 / Ss] * Dd * Dd + (size_t)qtr * 128 * Dd;
    float acc[2][2][4] = {};
    tc64_core(xn + (size_t)qtr * 128, Dd, W, 128, Dd, m0, n0, threadIdx.x, acc);
    tc64_store(acc, part + (size_t)z * TOK * Dd, Dd, m0, n0, threadIdx.x);
}

// ---------------- fused qkv reduce (4 partials each) + rope ----------------
__global__ void qkvrope_k(const float* __restrict__ part,
                          float* __restrict__ q, float* __restrict__ k, float* __restrict__ v) {
    int t = blockIdx.x;
    int s = t % Ss;
    int i = threadIdx.x;          // pair index 0..255
    int d0 = 2*i;
    int base = t*Dd + d0;
    float q0=0, q1=0, k0=0, k1=0, v0=0, v1=0;
    #pragma unroll
    for (int z = 0; z < 4; z++) {
        const float* pq = part + (size_t)z      * TOK*Dd + base;
        const float* pk = part + (size_t)(4+z)  * TOK*Dd + base;
        const float* pv = part + (size_t)(8+z)  * TOK*Dd + base;
        q0 += pq[0]; q1 += pq[1];
        k0 += pk[0]; k1 += pk[1];
        v0 += pv[0]; v1 += pv[1];
    }
    int j = i & 31;               // pair within head
    float inv = powf(10000.f, -(2.f*j) / 64.f);
    float ang = (float)s * inv;
    float c = cosf(ang), sn = sinf(ang);
    q[base]   = q0*c - q1*sn;
    q[base+1] = q0*sn + q1*c;
    k[base]   = k0*c - k1*sn;
    k[base+1] = k0*sn + k1*c;
    v[base]   = v0;
    v[base+1] = v1;
}

// ---------------- fused Wo reduce (4 partials) + residual + rmsnorm(n2) ------
__global__ void rednorm_k(float* __restrict__ x, const float* __restrict__ part,
                          const float* __restrict__ w, const int* __restrict__ cur,
                          float* __restrict__ out) {
    int t = blockIdx.x;
    int d = threadIdx.x;          // 512
    __shared__ float red[512];
    int idx = t*Dd + d;
    float v = x[idx];
    #pragma unroll
    for (int z = 0; z < 4; z++) v += part[(size_t)z*TOK*Dd + idx];
    x[idx] = v;
    red[d] = v*v;
    __syncthreads();
    for (int s = 256; s > 0; s >>= 1) {
        if (d < s) red[d] += red[d+s];
        __syncthreads();
    }
    float scale = rsqrtf(red[0] * (1.0f/Dd) + 1e-6f);
    out[idx] = v * scale * w[(size_t)cur[t / Ss] * Dd + d];
}

// ---------------- W1 reduce (2 partials) + silu -> ff ----------------
__global__ void w1red_k(const float* __restrict__ part, float* __restrict__ ff) {
    int i = blockIdx.x*256 + threadIdx.x;
    float s = part[i] + part[(size_t)TOK*Ff + i];
    ff[i] = s / (1.f + expf(-s));
}

// ---------------- W2 reduce (8 partials) + residual + pooling ----------------
__global__ void redpool_k(float* __restrict__ x, const float* __restrict__ part,
                          float* __restrict__ pooled) {
    int b = blockIdx.y;
    int d = blockIdx.x*128 + threadIdx.x;
    float acc = 0.f;
    for (int s = 0; s < Ss; s++) {
        int idx = (b*Ss + s)*Dd + d;
        float v = x[idx];
        #pragma unroll
        for (int z = 0; z < 8; z++) v += part[(size_t)z*TOK*Dd + idx];
        x[idx] = v;
        acc += v;
    }
    pooled[b*Dd + d] = acc * (1.f/Ss);
}

// ---------------- causal attention: block per (b,h,q-row) ----------------
__global__ void attn_k(const float* __restrict__ q, const float* __restrict__ k,
                       const float* __restrict__ v, float* __restrict__ o) {
    int qi = blockIdx.x, h = blockIdx.y, b = blockIdx.z;
    int tid = threadIdx.x;            // 256
    __shared__ float qv[HD];
    __shared__ float p[Ss];
    __shared__ float red[Ss];
    int base_bh = b*Ss*Dd + h*HD;
    if (tid < HD) qv[tid] = q[base_bh + qi*Dd + tid];
    __syncthreads();

    float s;
    if (tid <= qi) {
        const float* kp = &k[base_bh + tid*Dd];
        s = 0.f;
        #pragma unroll
        for (int d2 = 0; d2 < HD; d2++) s += qv[d2] * kp[d2];
        s *= 0.125f;
    } else {
        s = -1e30f;
    }
    red[tid] = s; __syncthreads();
    for (int st = 128; st > 0; st >>= 1) {
        if (tid < st) red[tid] = fmaxf(red[tid], red[tid+st]);
        __syncthreads();
    }
    float mx = red[0];
    __syncthreads();
    float e = expf(s - mx);
    p[tid] = e;
    red[tid] = e; __syncthreads();
    for (int st = 128; st > 0; st >>= 1) {
        if (tid < st) red[tid] += red[tid+st];
        __syncthreads();
    }
    float inv = 1.f / red[0];
    __syncthreads();

    int d = tid & 63, grp = tid >> 6;
    float acc = 0.f;
    for (int t2 = grp; t2 <= qi; t2 += 4)
        acc += p[t2] * v[base_bh + t2*Dd + d];
    red[tid] = acc;
    __syncthreads();
    if (tid < HD)
        o[base_bh + qi*Dd + tid] =
            (red[tid] + red[tid+64] + red[tid+128] + red[tid+192]) * inv;
}

// ---------------- gating + routing (single block, reads pooled) ----------------
__global__ void gate_k(const float* __restrict__ pooled, const float* __restrict__ gw) {
    __shared__ float red[512];
    __shared__ float sc[2*(Cc+1)];
    int tid = threadIdx.x;            // 512
    for (int idx = 0; idx < 2*(Cc+1); idx++) {
        int b = idx / (Cc+1), c = idx % (Cc+1);
        red[tid] = pooled[b*Dd + tid] * gw[tid*(Cc+1) + c];
        __syncthreads();
        for (int s = 256; s > 0; s >>= 1) {
            if (tid < s) red[tid] += red[tid+s];
            __syncthreads();
        }
        if (tid == 0) sc[idx] = red[0];
        __syncthreads();
    }
    if (tid == 0) {
        float p[Bb][Cc+1];
        for (int b = 0; b < Bb; b++) {
            float mx = -1e30f;
            for (int c = 0; c < Cc+1; c++) mx = fmaxf(mx, sc[b*(Cc+1)+c]);
            float sum = 0.f;
            for (int c = 0; c < Cc+1; c++) { p[b][c] = expf(sc[b*(Cc+1)+c] - mx); sum += p[b][c]; }
            for (int c = 0; c < Cc+1; c++) p[b][c] /= sum;
        }
        float lb = 0.f;
        for (int c = 0; c < Cc+1; c++) {
            g_accp[c] += p[0][c] + p[1][c];
            float avg = 0.5f * (p[0][c] + p[1][c]);
            lb += avg*avg;
        }
        g_acclb += (float)(Cc+1) * lb;
        for (int b = 0; b < Bb; b++) {
            int co = g_cur[b];
            int j1 = (co+1) & 3, j2 = (co+2) & 3;
            float s1 = sc[b*(Cc+1)+j1], s2 = sc[b*(Cc+1)+j2];
            int w;
            if (s1 > s2) w = j1;
            else if (s2 > s1) w = j2;
            else w = (j1 < j2) ? j1 : j2;
            g_cur[b] = w;
        }
    }
}

// ---------------- finalize aux losses ----------------
__global__ void fin_k(float* __restrict__ out, int n) {
    if (threadIdx.x == 0) {
        float avg[Cc+1];
        float m = 0.f;
        for (int i = 0; i < Cc+1; i++) { avg[i] = g_accp[i] * 0.25f; m += avg[i]; }
        m *= 1.f/(Cc+1);
        float var = 0.f;
        for (int i = 0; i < Cc+1; i++) { float d = avg[i] - m; var += d*d; }
        var *= 1.f/(Cc+1);
        out[n-2] = var;
        out[n-1] = g_acclb * 0.5f;
    }
}

// ---------------- host orchestration ----------------
extern "C" void kernel_launch(void* const* d_in, const int* in_sizes, int n_in,
                              void* d_out, int out_size) {
    const int*   ids   = (const int*)  d_in[0];
    const int*   start = (const int*)  d_in[1];
    const float* emb   = (const float*)d_in[2];
    const float* Wq    = (const float*)d_in[3];
    const float* Wk    = (const float*)d_in[4];
    const float* Wv    = (const float*)d_in[5];
    const float* Wo    = (const float*)d_in[6];
    const float* W1    = (const float*)d_in[7];
    const float* W2    = (const float*)d_in[8];
    const float* n1    = (const float*)d_in[9];
    const float* n2    = (const float*)d_in[10];
    const float* gw    = (const float*)d_in[11];
    const float* fnw   = (const float*)d_in[12];
    const float* fcw   = (const float*)d_in[13];
    float* out = (float*)d_out;

    float *x, *xn, *q, *k, *v, *o, *ff, *part, *pool;
    int* cur;
    cudaGetSymbolAddress((void**)&x,  g_x);
    cudaGetSymbolAddress((void**)&xn, g_xn);
    cudaGetSymbolAddress((void**)&q,  g_q);
    cudaGetSymbolAddress((void**)&k,  g_k);
    cudaGetSymbolAddress((void**)&v,  g_v);
    cudaGetSymbolAddress((void**)&o,  g_o);
    cudaGetSymbolAddress((void**)&ff, g_ff);
    cudaGetSymbolAddress((void**)&part, g_part);
    cudaGetSymbolAddress((void**)&pool, g_pool);
    cudaGetSymbolAddress((void**)&cur, g_cur);

    static int smem_set = 0;
    if (!smem_set) {
        cudaFuncSetAttribute(gemm_tc, cudaFuncAttributeMaxDynamicSharedMemorySize, TC_SMEM);
        smem_set = 1;
    }

    init_k<<<1, 32>>>(start);
    embed_k<<<TOK, Dd>>>(ids, emb, x);

    dim3 gqkv(Dd/64, TOK/64, 12);     // 768 blocks (split-K=4 x q,k,v)
    dim3 gwo (Dd/64, TOK/64, 4);      // 256 blocks (split-K=4, klen=128)
    dim3 gw1 (Ff/64, TOK/64, 2);      // 512 blocks (split-K=2, klen=256)
    dim3 gw2 (Dd/64, TOK/64, 8);      // 512 blocks (split-K=8, klen=256)
    for (int step = 0; step < 2; step++) {
        rmsnorm_k<<<TOK, Dd>>>(x, n1, cur, xn);
        qkv_sk<<<gqkv, 256>>>(xn, Wq, Wk, Wv, part, cur);
        qkvrope_k<<<TOK, 256>>>(part, q, k, v);
        attn_k<<<dim3(Ss, Hh, Bb), 256>>>(q, k, v, o);
        gemm_sk<<<gwo, 256>>>(o, Wo, part, cur, Dd, 128, Dd);
        rednorm_k<<<TOK, Dd>>>(x, part, n2, cur, xn);
        gemm_sk<<<gw1, 256>>>(xn, W1, part, cur, Dd, 256, Ff);
        w1red_k<<<TOK*Ff/256, 256>>>(part, ff);
        gemm_sk<<<gw2, 256>>>(ff, W2, part, cur, Ff, 256, Dd);
        redpool_k<<<dim3(Dd/128, Bb), 128>>>(x, part, pool);
        gate_k<<<1, 512>>>(pool, gw);
    }
    rmsnorm_k<<<TOK, Dd>>>(x, fnw, nullptr, xn);
    gemm_tc<<<dim3(TOK/128, Vv/128), 256, TC_SMEM>>>(xn, fcw, out, Dd, Vv);
    fin_k<<<1, 32>>>(out, out_size);
}

// round 9
// speedup vs baseline: 1.7243x; 1.7243x over previous
#include <cuda_runtime.h>
#include <math.h>
#include <stdint.h>

#define Dd  512
#define Hh  8
#define HD  64
#define Bb  2
#define Ss  256
#define Ff  2048
#define Cc  4
#define Vv  32000
#define TOK (Bb*Ss)   // 512

// ---------------- device state (no allocation allowed) ----------------
__device__ float g_x [TOK*Dd];
__device__ float g_xn[TOK*Dd];
__device__ float g_q [TOK*Dd];
__device__ float g_k [TOK*Dd];
__device__ float g_v [TOK*Dd];
__device__ float g_o [TOK*Dd];
__device__ float g_ff[TOK*Ff];
__device__ float g_part[6*TOK*Dd];
__device__ float g_pool[Bb*Dd];
__device__ int   g_cur[Bb];
__device__ float g_accp[Cc+1];
__device__ float g_acclb;

// ---------------- fused embed + init + first rmsnorm (cur = start) ----------------
__global__ void embednorm_k(const int* __restrict__ ids, const int* __restrict__ start,
                            const float* __restrict__ emb, const float* __restrict__ n1,
                            float* __restrict__ x, float* __restrict__ out) {
    int t = blockIdx.x;           // token
    int d = threadIdx.x;          // 512
    __shared__ float red[512];
    if (t == 0 && d == 0) {       // fold init_k
        g_cur[0] = start[0];
        g_cur[1] = start[1];
        #pragma unroll
        for (int i = 0; i < Cc+1; i++) g_accp[i] = 0.f;
        g_acclb = 0.f;
    }
    float v = emb[(size_t)ids[t]*Dd + d] * sqrtf((float)Dd);
    x[t*Dd + d] = v;
    red[d] = v*v;
    __syncthreads();
    for (int s = 256; s > 0; s >>= 1) {
        if (d < s) red[d] += red[d+s];
        __syncthreads();
    }
    float scale = rsqrtf(red[0] * (1.0f/Dd) + 1e-6f);
    out[t*Dd + d] = v * scale * n1[(size_t)start[t / Ss] * Dd + d];
}

// ---------------- rmsnorm (block per token) ----------------
__global__ void rmsnorm_k(const float* __restrict__ x, const float* __restrict__ w,
                          const int* __restrict__ cur, float* __restrict__ out) {
    int t = blockIdx.x;
    int d = threadIdx.x;          // 512
    __shared__ float red[512];
    float v = x[t*Dd + d];
    red[d] = v*v;
    __syncthreads();
    for (int s = 256; s > 0; s >>= 1) {
        if (d < s) red[d] += red[d+s];
        __syncthreads();
    }
    float scale = rsqrtf(red[0] * (1.0f/Dd) + 1e-6f);
    const float* ww = w;
    if (cur) ww += (size_t)cur[t / Ss] * Dd;
    out[t*Dd + d] = v * scale * ww[d];
}

// ---------------- tf32 / cp.async helpers ----------------
__device__ __forceinline__ uint32_t f2tf32(float f) {
    uint32_t u;
    asm volatile("cvt.rna.tf32.f32 %0, %1;" : "=r"(u) : "f"(f));
    return u;
}

__device__ __forceinline__ void mma_tf32(float c[4],
    uint32_t a0, uint32_t a1, uint32_t a2, uint32_t a3,
    uint32_t b0, uint32_t b1)
{
    asm volatile(
        "mma.sync.aligned.m16n8k8.row.col.f32.tf32.tf32.f32 "
        "{%0,%1,%2,%3}, {%4,%5,%6,%7}, {%8,%9}, {%0,%1,%2,%3};"
        : "+f"(c[0]), "+f"(c[1]), "+f"(c[2]), "+f"(c[3])
        : "r"(a0), "r"(a1), "r"(a2), "r"(a3), "r"(b0), "r"(b1));
}

__device__ __forceinline__ void cp_async16(float* smem, const float* gmem) {
    uint32_t s;
    asm("{ .reg .u64 t; cvta.to.shared.u64 t, %1; cvt.u32.u64 %0, t; }"
        : "=r"(s) : "l"(smem));
    asm volatile("cp.async.cg.shared.global [%0], [%1], 16;" :: "r"(s), "l"(gmem) : "memory");
}
#define CP_COMMIT()  asm volatile("cp.async.commit_group;" ::: "memory")
#define CP_WAIT1()   asm volatile("cp.async.wait_group 1;" ::: "memory")
#define CP_WAIT0()   asm volatile("cp.async.wait_group 0;" ::: "memory")

// ---------------- tensor-core logits GEMM (verified) + fused aux write ------
#define TC_SMEM ((2*128*36 + 2*32*136) * (int)sizeof(float))
__global__ void __launch_bounds__(256,2) gemm_tc(
    const float* __restrict__ A, const float* __restrict__ W,
    float* __restrict__ Out, int K, int N, int aux_n)
{
    extern __shared__ float dsm[];
    float (*As)[128][36]  = (float(*)[128][36])dsm;
    float (*Bs)[32][136]  = (float(*)[32][136])(dsm + 2*128*36);
    int tid = threadIdx.x;
    int m0 = blockIdx.x*128, n0 = blockIdx.y*128;
    int warp = tid >> 5, lane = tid & 31;
    int wm = warp & 1, wn = warp >> 1;
    int g = lane >> 2, tg = lane & 3;

    // fused fin_k: aux losses from accumulated gate state
    if (blockIdx.x == 0 && blockIdx.y == 0 && tid == 0 && aux_n > 0) {
        float avg[Cc+1];
        float m = 0.f;
        #pragma unroll
        for (int i = 0; i < Cc+1; i++) { avg[i] = g_accp[i] * 0.25f; m += avg[i]; }
        m *= 1.f/(Cc+1);
        float var = 0.f;
        #pragma unroll
        for (int i = 0; i < Cc+1; i++) { float d = avg[i] - m; var += d*d; }
        var *= 1.f/(Cc+1);
        Out[aux_n-2] = var;
        Out[aux_n-1] = g_acclb * 0.5f;
    }

    auto issue = [&](int k0, int buf) {
        #pragma unroll
        for (int l = 0; l < 4; l++) {
            int idx = tid + l*256;
            int row = idx >> 3, kc = (idx & 7) * 4;
            cp_async16(&As[buf][row][kc], &A[(size_t)(m0+row)*K + k0 + kc]);
        }
        #pragma unroll
        for (int l = 0; l < 4; l++) {
            int idx = tid + l*256;
            int kr = idx >> 5, nc = (idx & 31) * 4;
            cp_async16(&Bs[buf][kr][nc], &W[(size_t)(k0+kr)*N + n0 + nc]);
        }
        CP_COMMIT();
    };

    float acc[4][4][4] = {};
    int nk = K / 32;
    issue(0, 0);
    int buf = 0;
    for (int it = 0; it < nk; it++) {
        bool more = (it + 1) < nk;
        if (more) issue((it+1)*32, buf^1);
        if (more) CP_WAIT1(); else CP_WAIT0();
        __syncthreads();

        #pragma unroll
        for (int kk = 0; kk < 32; kk += 8) {
            uint32_t af[4][4], bf[4][2];
            #pragma unroll
            for (int mt = 0; mt < 4; mt++) {
                int mrow = wm*64 + mt*16 + g;
                af[mt][0] = f2tf32(As[buf][mrow  ][kk+tg]);
                af[mt][1] = f2tf32(As[buf][mrow+8][kk+tg]);
                af[mt][2] = f2tf32(As[buf][mrow  ][kk+tg+4]);
                af[mt][3] = f2tf32(As[buf][mrow+8][kk+tg+4]);
            }
            #pragma unroll
            for (int nt = 0; nt < 4; nt++) {
                int ncol = wn*32 + nt*8 + g;
                bf[nt][0] = f2tf32(Bs[buf][kk+tg  ][ncol]);
                bf[nt][1] = f2tf32(Bs[buf][kk+tg+4][ncol]);
            }
            #pragma unroll
            for (int mt = 0; mt < 4; mt++)
                #pragma unroll
                for (int nt = 0; nt < 4; nt++)
                    mma_tf32(acc[mt][nt], af[mt][0], af[mt][1], af[mt][2], af[mt][3],
                             bf[nt][0], bf[nt][1]);
        }
        __syncthreads();
        buf ^= 1;
    }

    #pragma unroll
    for (int mt = 0; mt < 4; mt++) {
        #pragma unroll
        for (int nt = 0; nt < 4; nt++) {
            int row = m0 + wm*64 + mt*16 + g;
            int col = n0 + wn*32 + nt*8 + 2*tg;
            float2 lo = { acc[mt][nt][0], acc[mt][nt][1] };
            float2 hi = { acc[mt][nt][2], acc[mt][nt][3] };
            *(float2*)&Out[(size_t)row*N + col]     = lo;
            *(float2*)&Out[(size_t)(row+8)*N + col] = hi;
        }
    }
}

// ---------------- tf32x3 mid GEMM core (verified R7) ----------------
__device__ __forceinline__ void tc64_core(
    const float* __restrict__ A, int lda, const float* __restrict__ W,
    int K, int N, int m0, int n0, int tid, float acc[2][2][4])
{
    __shared__ float As[2][64][36];
    __shared__ float Bs[2][32][72];
    int warp = tid >> 5, lane = tid & 31;
    int wm = warp & 1, wn = warp >> 1;
    int g = lane >> 2, tg = lane & 3;

    auto issue = [&](int k0, int buf) {
        #pragma unroll
        for (int l = 0; l < 2; l++) {
            int idx = tid + l*256;
            int row = idx >> 3, kc = (idx & 7) * 4;
            cp_async16(&As[buf][row][kc], &A[(size_t)(m0+row)*lda + k0 + kc]);
        }
        #pragma unroll
        for (int l = 0; l < 2; l++) {
            int idx = tid + l*256;
            int kr = idx >> 4, nc = (idx & 15) * 4;
            cp_async16(&Bs[buf][kr][nc], &W[(size_t)(k0+kr)*N + n0 + nc]);
        }
        CP_COMMIT();
    };

    int nk = K / 32;
    issue(0, 0);
    int buf = 0;
    for (int it = 0; it < nk; it++) {
        bool more = (it + 1) < nk;
        if (more) issue((it+1)*32, buf^1);
        if (more) CP_WAIT1(); else CP_WAIT0();
        __syncthreads();

        #pragma unroll
        for (int kk = 0; kk < 32; kk += 8) {
            uint32_t ah[2][4], al[2][4], bh[2][2], bl[2][2];
            #pragma unroll
            for (int mt = 0; mt < 2; mt++) {
                int mrow = wm*32 + mt*16 + g;
                float a0 = As[buf][mrow  ][kk+tg];
                float a1 = As[buf][mrow+8][kk+tg];
                float a2 = As[buf][mrow  ][kk+tg+4];
                float a3 = As[buf][mrow+8][kk+tg+4];
                ah[mt][0] = f2tf32(a0); al[mt][0] = f2tf32(a0 - __uint_as_float(ah[mt][0]));
                ah[mt][1] = f2tf32(a1); al[mt][1] = f2tf32(a1 - __uint_as_float(ah[mt][1]));
                ah[mt][2] = f2tf32(a2); al[mt][2] = f2tf32(a2 - __uint_as_float(ah[mt][2]));
                ah[mt][3] = f2tf32(a3); al[mt][3] = f2tf32(a3 - __uint_as_float(ah[mt][3]));
            }
            #pragma unroll
            for (int nt = 0; nt < 2; nt++) {
                int ncol = wn*16 + nt*8 + g;
                float b0 = Bs[buf][kk+tg  ][ncol];
                float b1 = Bs[buf][kk+tg+4][ncol];
                bh[nt][0] = f2tf32(b0); bl[nt][0] = f2tf32(b0 - __uint_as_float(bh[nt][0]));
                bh[nt][1] = f2tf32(b1); bl[nt][1] = f2tf32(b1 - __uint_as_float(bh[nt][1]));
            }
            #pragma unroll
            for (int mt = 0; mt < 2; mt++)
                #pragma unroll
                for (int nt = 0; nt < 2; nt++) {
                    mma_tf32(acc[mt][nt], ah[mt][0], ah[mt][1], ah[mt][2], ah[mt][3],
                             bl[nt][0], bl[nt][1]);
                    mma_tf32(acc[mt][nt], al[mt][0], al[mt][1], al[mt][2], al[mt][3],
                             bh[nt][0], bh[nt][1]);
                    mma_tf32(acc[mt][nt], ah[mt][0], ah[mt][1], ah[mt][2], ah[mt][3],
                             bh[nt][0], bh[nt][1]);
                }
        }
        __syncthreads();
        buf ^= 1;
    }
}

// shared epilogue for 64x64 tc tiles
__device__ __forceinline__ void tc64_epilogue(
    float acc[2][2][4], const float* __restrict__ res, float* __restrict__ Out,
    int N, int m0, int n0, int tid, int epi)
{
    int warp = tid >> 5, lane = tid & 31;
    int wm = warp & 1, wn = warp >> 1;
    int g = lane >> 2, tg = lane & 3;
    #pragma unroll
    for (int mt = 0; mt < 2; mt++) {
        #pragma unroll
        for (int nt = 0; nt < 2; nt++) {
            int row = m0 + wm*32 + mt*16 + g;
            int col = n0 + wn*16 + nt*8 + 2*tg;
            float2 lo = { acc[mt][nt][0], acc[mt][nt][1] };
            float2 hi = { acc[mt][nt][2], acc[mt][nt][3] };
            if (epi == 1) {
                float2 r0 = *(const float2*)&res[(size_t)row*N + col];
                float2 r1 = *(const float2*)&res[(size_t)(row+8)*N + col];
                lo.x += r0.x; lo.y += r0.y;
                hi.x += r1.x; hi.y += r1.y;
            } else if (epi == 2) {
                lo.x = lo.x / (1.f + expf(-lo.x));
                lo.y = lo.y / (1.f + expf(-lo.y));
                hi.x = hi.x / (1.f + expf(-hi.x));
                hi.y = hi.y / (1.f + expf(-hi.y));
            }
            *(float2*)&Out[(size_t)row*N + col]     = lo;
            *(float2*)&Out[(size_t)(row+8)*N + col] = hi;
        }
    }
}

// ---------------- mid GEMM, direct (used for W1) ----------------
__global__ void __launch_bounds__(256) gemm_mid_tc(
    const float* __restrict__ A, const float* __restrict__ Wb,
    const float* __restrict__ res, float* __restrict__ Out,
    const int* __restrict__ cur, int K, int N, int epi)
{
    int m0 = blockIdx.y*64, n0 = blockIdx.x*64;
    const float* W = Wb;
    if (cur) W += (size_t)cur[m0 / Ss] * K * N;
    float acc[2][2][4] = {};
    tc64_core(A, K, W, K, N, m0, n0, threadIdx.x, acc);
    tc64_epilogue(acc, res, Out, N, m0, n0, threadIdx.x, epi);
}

// ---------------- split-K mid GEMM -> partials (N = Dd) ----------------
__global__ void __launch_bounds__(256) gemm_sk(
    const float* __restrict__ A, const float* __restrict__ Wb,
    float* __restrict__ part, const int* __restrict__ cur, int Kfull, int klen)
{
    int m0 = blockIdx.y*64, n0 = blockIdx.x*64;
    int z = blockIdx.z;
    const float* W = Wb + (size_t)cur[m0 / Ss] * Kfull * Dd + (size_t)z * klen * Dd;
    float acc[2][2][4] = {};
    tc64_core(A + (size_t)z * klen, Kfull, W, klen, Dd, m0, n0, threadIdx.x, acc);
    tc64_epilogue(acc, nullptr, part + (size_t)z * TOK * Dd, Dd, m0, n0, threadIdx.x, 0);
}

// ---------------- split-K QKV -> 6 partials ----------------
// grid.z in [0,6): op = z>>1 (0=q,1=k,2=v), half = z&1
__global__ void __launch_bounds__(256) qkv_sk(
    const float* __restrict__ xn,
    const float* __restrict__ Wq, const float* __restrict__ Wk, const float* __restrict__ Wv,
    float* __restrict__ part, const int* __restrict__ cur)
{
    int z = blockIdx.z;
    int op = z >> 1, half = z & 1;
    const float* Wb = (op == 0) ? Wq : (op == 1) ? Wk : Wv;
    int m0 = blockIdx.y*64, n0 = blockIdx.x*64;
    const float* W = Wb + (size_t)cur[m0 / Ss] * Dd * Dd + (size_t)half * 256 * Dd;
    float acc[2][2][4] = {};
    tc64_core(xn + (size_t)half * 256, Dd, W, 256, Dd, m0, n0, threadIdx.x, acc);
    tc64_epilogue(acc, nullptr, part + (size_t)z * TOK * Dd, Dd, m0, n0, threadIdx.x, 0);
}

// ---------------- fused qkv reduce (2 partials each) + rope ----------------
// layout: partials [q0,q1,k0,k1,v0,v1]
__global__ void qkvrope_k(const float* __restrict__ part,
                          float* __restrict__ q, float* __restrict__ k, float* __restrict__ v) {
    int t = blockIdx.x;
    int s = t % Ss;
    int i = threadIdx.x;          // pair index 0..255
    int base = t*Dd + 2*i;
    float q0=0, q1=0, k0=0, k1=0, v0=0, v1=0;
    #pragma unroll
    for (int z = 0; z < 2; z++) {
        const float* pq = part + (size_t)z      * TOK*Dd + base;
        const float* pk = part + (size_t)(2+z)  * TOK*Dd + base;
        const float* pv = part + (size_t)(4+z)  * TOK*Dd + base;
        q0 += pq[0]; q1 += pq[1];
        k0 += pk[0]; k1 += pk[1];
        v0 += pv[0]; v1 += pv[1];
    }
    int j = i & 31;               // pair within head
    float inv = powf(10000.f, -(2.f*j) / 64.f);
    float ang = (float)s * inv;
    float c = cosf(ang), sn = sinf(ang);
    q[base]   = q0*c - q1*sn;
    q[base+1] = q0*sn + q1*c;
    k[base]   = k0*c - k1*sn;
    k[base+1] = k0*sn + k1*c;
    v[base]   = v0;
    v[base+1] = v1;
}

// ---------------- fused Wo reduce (2 partials) + residual + rmsnorm(n2) ------
__global__ void rednorm_k(float* __restrict__ x, const float* __restrict__ part,
                          const float* __restrict__ w, const int* __restrict__ cur,
                          float* __restrict__ out) {
    int t = blockIdx.x;
    int d = threadIdx.x;          // 512
    __shared__ float red[512];
    int idx = t*Dd + d;
    float v = x[idx];
    #pragma unroll
    for (int z = 0; z < 2; z++) v += part[(size_t)z*TOK*Dd + idx];
    x[idx] = v;
    red[d] = v*v;
    __syncthreads();
    for (int s = 256; s > 0; s >>= 1) {
        if (d < s) red[d] += red[d+s];
        __syncthreads();
    }
    float scale = rsqrtf(red[0] * (1.0f/Dd) + 1e-6f);
    out[idx] = v * scale * w[(size_t)cur[t / Ss] * Dd + d];
}

// ---------------- reduce: x += sum of S partials ----------------
__global__ void red_add(float* __restrict__ x, const float* __restrict__ part, int S) {
    int i = blockIdx.x*256 + threadIdx.x;
    float s = x[i];
    for (int j = 0; j < S; j++) s += part[(size_t)j*TOK*Dd + i];
    x[i] = s;
}

// ---------------- causal attention: block per (b,h,q-row) ----------------
__global__ void attn_k(const float* __restrict__ q, const float* __restrict__ k,
                       const float* __restrict__ v, float* __restrict__ o) {
    int qi = blockIdx.x, h = blockIdx.y, b = blockIdx.z;
    int tid = threadIdx.x;            // 256
    __shared__ float qv[HD];
    __shared__ float p[Ss];
    __shared__ float red[Ss];
    int base_bh = b*Ss*Dd + h*HD;
    if (tid < HD) qv[tid] = q[base_bh + qi*Dd + tid];
    __syncthreads();

    float s;
    if (tid <= qi) {
        const float* kp = &k[base_bh + tid*Dd];
        s = 0.f;
        #pragma unroll
        for (int d2 = 0; d2 < HD; d2++) s += qv[d2] * kp[d2];
        s *= 0.125f;
    } else {
        s = -1e30f;
    }
    red[tid] = s; __syncthreads();
    for (int st = 128; st > 0; st >>= 1) {
        if (tid < st) red[tid] = fmaxf(red[tid], red[tid+st]);
        __syncthreads();
    }
    float mx = red[0];
    __syncthreads();
    float e = expf(s - mx);
    p[tid] = e;
    red[tid] = e; __syncthreads();
    for (int st = 128; st > 0; st >>= 1) {
        if (tid < st) red[tid] += red[tid+st];
        __syncthreads();
    }
    float inv = 1.f / red[0];
    __syncthreads();

    int d = tid & 63, grp = tid >> 6;
    float acc = 0.f;
    for (int t2 = grp; t2 <= qi; t2 += 4)
        acc += p[t2] * v[base_bh + t2*Dd + d];
    red[tid] = acc;
    __syncthreads();
    if (tid < HD)
        o[base_bh + qi*Dd + tid] =
            (red[tid] + red[tid+64] + red[tid+128] + red[tid+192]) * inv;
}

// ---------------- parallel pooling ----------------
__global__ void pool_k(const float* __restrict__ x, float* __restrict__ pooled) {
    int b = blockIdx.y;
    int d = blockIdx.x*128 + threadIdx.x;
    float s = 0.f;
    #pragma unroll 4
    for (int ss = 0; ss < Ss; ss++) s += x[(size_t)(b*Ss+ss)*Dd + d];
    pooled[b*Dd + d] = s * (1.f/Ss);
}

// ---------------- gating + routing (single block, reads pooled) ----------------
__global__ void gate_k(const float* __restrict__ pooled, const float* __restrict__ gw) {
    __shared__ float red[512];
    __shared__ float sc[2*(Cc+1)];
    int tid = threadIdx.x;            // 512
    for (int idx = 0; idx < 2*(Cc+1); idx++) {
        int b = idx / (Cc+1), c = idx % (Cc+1);
        red[tid] = pooled[b*Dd + tid] * gw[tid*(Cc+1) + c];
        __syncthreads();
        for (int s = 256; s > 0; s >>= 1) {
            if (tid < s) red[tid] += red[tid+s];
            __syncthreads();
        }
        if (tid == 0) sc[idx] = red[0];
        __syncthreads();
    }
    if (tid == 0) {
        float p[Bb][Cc+1];
        for (int b = 0; b < Bb; b++) {
            float mx = -1e30f;
            for (int c = 0; c < Cc+1; c++) mx = fmaxf(mx, sc[b*(Cc+1)+c]);
            float sum = 0.f;
            for (int c = 0; c < Cc+1; c++) { p[b][c] = expf(sc[b*(Cc+1)+c] - mx); sum += p[b][c]; }
            for (int c = 0; c < Cc+1; c++) p[b][c] /= sum;
        }
        float lb = 0.f;
        for (int c = 0; c < Cc+1; c++) {
            g_accp[c] += p[0][c] + p[1][c];
            float avg = 0.5f * (p[0][c] + p[1][c]);
            lb += avg*avg;
        }
        g_acclb += (float)(Cc+1) * lb;
        for (int b = 0; b < Bb; b++) {
            int co = g_cur[b];
            int j1 = (co+1) & 3, j2 = (co+2) & 3;
            float s1 = sc[b*(Cc+1)+j1], s2 = sc[b*(Cc+1)+j2];
            int w;
            if (s1 > s2) w = j1;
            else if (s2 > s1) w = j2;
            else w = (j1 < j2) ? j1 : j2;
            g_cur[b] = w;
        }
    }
}

// ---------------- host orchestration ----------------
extern "C" void kernel_launch(void* const* d_in, const int* in_sizes, int n_in,
                              void* d_out, int out_size) {
    const int*   ids   = (const int*)  d_in[0];
    const int*   start = (const int*)  d_in[1];
    const float* emb   = (const float*)d_in[2];
    const float* Wq    = (const float*)d_in[3];
    const float* Wk    = (const float*)d_in[4];
    const float* Wv    = (const float*)d_in[5];
    const float* Wo    = (const float*)d_in[6];
    const float* W1    = (const float*)d_in[7];
    const float* W2    = (const float*)d_in[8];
    const float* n1    = (const float*)d_in[9];
    const float* n2    = (const float*)d_in[10];
    const float* gw    = (const float*)d_in[11];
    const float* fnw   = (const float*)d_in[12];
    const float* fcw   = (const float*)d_in[13];
    float* out = (float*)d_out;

    float *x, *xn, *q, *k, *v, *o, *ff, *part, *pool;
    int* cur;
    cudaGetSymbolAddress((void**)&x,  g_x);
    cudaGetSymbolAddress((void**)&xn, g_xn);
    cudaGetSymbolAddress((void**)&q,  g_q);
    cudaGetSymbolAddress((void**)&k,  g_k);
    cudaGetSymbolAddress((void**)&v,  g_v);
    cudaGetSymbolAddress((void**)&o,  g_o);
    cudaGetSymbolAddress((void**)&ff, g_ff);
    cudaGetSymbolAddress((void**)&part, g_part);
    cudaGetSymbolAddress((void**)&pool, g_pool);
    cudaGetSymbolAddress((void**)&cur, g_cur);

    static int smem_set = 0;
    if (!smem_set) {
        cudaFuncSetAttribute(gemm_tc, cudaFuncAttributeMaxDynamicSharedMemorySize, TC_SMEM);
        smem_set = 1;
    }

    embednorm_k<<<TOK, Dd>>>(ids, start, emb, n1, x, xn);

    int nred = TOK*Dd/256;            // 1024 blocks
    dim3 gqkv(Dd/64, TOK/64, 6);      // 384 blocks (split-K=2 x q,k,v)
    dim3 gwo (Dd/64, TOK/64, 2);      // 128 blocks (split-K=2)
    dim3 gw1 (Ff/64, TOK/64);         // 256 blocks
    dim3 gw2 (Dd/64, TOK/64, 4);      // 256 blocks (split-K=4)
    for (int step = 0; step < 2; step++) {
        if (step > 0)
            rmsnorm_k<<<TOK, Dd>>>(x, n1, cur, xn);
        qkv_sk<<<gqkv, 256>>>(xn, Wq, Wk, Wv, part, cur);
        qkvrope_k<<<TOK, 256>>>(part, q, k, v);
        attn_k<<<dim3(Ss, Hh, Bb), 256>>>(q, k, v, o);
        gemm_sk<<<gwo, 256>>>(o, Wo, part, cur, Dd, 256);
        rednorm_k<<<TOK, Dd>>>(x, part, n2, cur, xn);
        gemm_mid_tc<<<gw1, 256>>>(xn, W1, nullptr, ff, cur, Dd, Ff, 2);
        gemm_sk<<<gw2, 256>>>(ff, W2, part, cur, Ff, 512);
        red_add<<<nred, 256>>>(x, part, 4);
        pool_k<<<dim3(Dd/128, Bb), 128>>>(x, pool);
        gate_k<<<1, 512>>>(pool, gw);
    }
    rmsnorm_k<<<TOK, Dd>>>(x, fnw, nullptr, xn);
    gemm_tc<<<dim3(TOK/128, Vv/128), 256, TC_SMEM>>>(xn, fcw, out, Dd, Vv, out_size);
}

// round 10
// speedup vs baseline: 2.3225x; 1.3469x over previous
#include <cuda_runtime.h>
#include <math.h>
#include <stdint.h>

#define Dd  512
#define Hh  8
#define HD  64
#define Bb  2
#define Ss  256
#define Ff  2048
#define Cc  4
#define Vv  32000
#define TOK (Bb*Ss)   // 512

// ---------------- device state (no allocation allowed) ----------------
__device__ float g_x [TOK*Dd];
__device__ float g_xn[TOK*Dd];
__device__ float g_q [TOK*Dd];
__device__ float g_k [TOK*Dd];
__device__ float g_v [TOK*Dd];
__device__ float g_o [TOK*Dd];
__device__ float g_ff[TOK*Ff];
__device__ float g_part[6*TOK*Dd];
__device__ float g_pool[Bb*Dd];
__device__ int   g_cur[Bb];
__device__ float g_accp[Cc+1];
__device__ float g_acclb;

// ---------------- fused embed + init + first rmsnorm (cur = start) ----------------
__global__ void embednorm_k(const int* __restrict__ ids, const int* __restrict__ start,
                            const float* __restrict__ emb, const float* __restrict__ n1,
                            float* __restrict__ x, float* __restrict__ out) {
    int t = blockIdx.x;
    int d = threadIdx.x;          // 512
    __shared__ float red[512];
    if (t == 0 && d == 0) {
        g_cur[0] = start[0];
        g_cur[1] = start[1];
        #pragma unroll
        for (int i = 0; i < Cc+1; i++) g_accp[i] = 0.f;
        g_acclb = 0.f;
    }
    float v = emb[(size_t)ids[t]*Dd + d] * sqrtf((float)Dd);
    x[t*Dd + d] = v;
    red[d] = v*v;
    __syncthreads();
    for (int s = 256; s > 0; s >>= 1) {
        if (d < s) red[d] += red[d+s];
        __syncthreads();
    }
    float scale = rsqrtf(red[0] * (1.0f/Dd) + 1e-6f);
    out[t*Dd + d] = v * scale * n1[(size_t)start[t / Ss] * Dd + d];
}

// ---------------- rmsnorm (block per token) ----------------
__global__ void rmsnorm_k(const float* __restrict__ x, const float* __restrict__ w,
                          const int* __restrict__ cur, float* __restrict__ out) {
    int t = blockIdx.x;
    int d = threadIdx.x;          // 512
    __shared__ float red[512];
    float v = x[t*Dd + d];
    red[d] = v*v;
    __syncthreads();
    for (int s = 256; s > 0; s >>= 1) {
        if (d < s) red[d] += red[d+s];
        __syncthreads();
    }
    float scale = rsqrtf(red[0] * (1.0f/Dd) + 1e-6f);
    const float* ww = w;
    if (cur) ww += (size_t)cur[t / Ss] * Dd;
    out[t*Dd + d] = v * scale * ww[d];
}

// ---------------- tf32 / cp.async helpers ----------------
__device__ __forceinline__ uint32_t f2tf32(float f) {
    uint32_t u;
    asm volatile("cvt.rna.tf32.f32 %0, %1;" : "=r"(u) : "f"(f));
    return u;
}

__device__ __forceinline__ void mma_tf32(float c[4],
    uint32_t a0, uint32_t a1, uint32_t a2, uint32_t a3,
    uint32_t b0, uint32_t b1)
{
    asm volatile(
        "mma.sync.aligned.m16n8k8.row.col.f32.tf32.tf32.f32 "
        "{%0,%1,%2,%3}, {%4,%5,%6,%7}, {%8,%9}, {%0,%1,%2,%3};"
        : "+f"(c[0]), "+f"(c[1]), "+f"(c[2]), "+f"(c[3])
        : "r"(a0), "r"(a1), "r"(a2), "r"(a3), "r"(b0), "r"(b1));
}

__device__ __forceinline__ void cp_async16(float* smem, const float* gmem) {
    uint32_t s;
    asm("{ .reg .u64 t; cvta.to.shared.u64 t, %1; cvt.u32.u64 %0, t; }"
        : "=r"(s) : "l"(smem));
    asm volatile("cp.async.cg.shared.global [%0], [%1], 16;" :: "r"(s), "l"(gmem) : "memory");
}
#define CP_COMMIT()  asm volatile("cp.async.commit_group;" ::: "memory")
#define CP_WAIT1()   asm volatile("cp.async.wait_group 1;" ::: "memory")
#define CP_WAIT0()   asm volatile("cp.async.wait_group 0;" ::: "memory")

// ---------------- tensor-core logits GEMM (verified) + fused aux write ------
#define TC_SMEM ((2*128*36 + 2*32*136) * (int)sizeof(float))
__global__ void __launch_bounds__(256,2) gemm_tc(
    const float* __restrict__ A, const float* __restrict__ W,
    float* __restrict__ Out, int K, int N, int aux_n)
{
    extern __shared__ float dsm[];
    float (*As)[128][36]  = (float(*)[128][36])dsm;
    float (*Bs)[32][136]  = (float(*)[32][136])(dsm + 2*128*36);
    int tid = threadIdx.x;
    int m0 = blockIdx.x*128, n0 = blockIdx.y*128;
    int warp = tid >> 5, lane = tid & 31;
    int wm = warp & 1, wn = warp >> 1;
    int g = lane >> 2, tg = lane & 3;

    if (blockIdx.x == 0 && blockIdx.y == 0 && tid == 0 && aux_n > 0) {
        float avg[Cc+1];
        float m = 0.f;
        #pragma unroll
        for (int i = 0; i < Cc+1; i++) { avg[i] = g_accp[i] * 0.25f; m += avg[i]; }
        m *= 1.f/(Cc+1);
        float var = 0.f;
        #pragma unroll
        for (int i = 0; i < Cc+1; i++) { float d = avg[i] - m; var += d*d; }
        var *= 1.f/(Cc+1);
        Out[aux_n-2] = var;
        Out[aux_n-1] = g_acclb * 0.5f;
    }

    auto issue = [&](int k0, int buf) {
        #pragma unroll
        for (int l = 0; l < 4; l++) {
            int idx = tid + l*256;
            int row = idx >> 3, kc = (idx & 7) * 4;
            cp_async16(&As[buf][row][kc], &A[(size_t)(m0+row)*K + k0 + kc]);
        }
        #pragma unroll
        for (int l = 0; l < 4; l++) {
            int idx = tid + l*256;
            int kr = idx >> 5, nc = (idx & 31) * 4;
            cp_async16(&Bs[buf][kr][nc], &W[(size_t)(k0+kr)*N + n0 + nc]);
        }
        CP_COMMIT();
    };

    float acc[4][4][4] = {};
    int nk = K / 32;
    issue(0, 0);
    int buf = 0;
    for (int it = 0; it < nk; it++) {
        bool more = (it + 1) < nk;
        if (more) issue((it+1)*32, buf^1);
        if (more) CP_WAIT1(); else CP_WAIT0();
        __syncthreads();

        #pragma unroll
        for (int kk = 0; kk < 32; kk += 8) {
            uint32_t af[4][4], bf[4][2];
            #pragma unroll
            for (int mt = 0; mt < 4; mt++) {
                int mrow = wm*64 + mt*16 + g;
                af[mt][0] = f2tf32(As[buf][mrow  ][kk+tg]);
                af[mt][1] = f2tf32(As[buf][mrow+8][kk+tg]);
                af[mt][2] = f2tf32(As[buf][mrow  ][kk+tg+4]);
                af[mt][3] = f2tf32(As[buf][mrow+8][kk+tg+4]);
            }
            #pragma unroll
            for (int nt = 0; nt < 4; nt++) {
                int ncol = wn*32 + nt*8 + g;
                bf[nt][0] = f2tf32(Bs[buf][kk+tg  ][ncol]);
                bf[nt][1] = f2tf32(Bs[buf][kk+tg+4][ncol]);
            }
            #pragma unroll
            for (int mt = 0; mt < 4; mt++)
                #pragma unroll
                for (int nt = 0; nt < 4; nt++)
                    mma_tf32(acc[mt][nt], af[mt][0], af[mt][1], af[mt][2], af[mt][3],
                             bf[nt][0], bf[nt][1]);
        }
        __syncthreads();
        buf ^= 1;
    }

    #pragma unroll
    for (int mt = 0; mt < 4; mt++) {
        #pragma unroll
        for (int nt = 0; nt < 4; nt++) {
            int row = m0 + wm*64 + mt*16 + g;
            int col = n0 + wn*32 + nt*8 + 2*tg;
            float2 lo = { acc[mt][nt][0], acc[mt][nt][1] };
            float2 hi = { acc[mt][nt][2], acc[mt][nt][3] };
            *(float2*)&Out[(size_t)row*N + col]     = lo;
            *(float2*)&Out[(size_t)(row+8)*N + col] = hi;
        }
    }
}

// ---------------- tf32x3 mid GEMM core (verified R7) ----------------
__device__ __forceinline__ void tc64_core(
    const float* __restrict__ A, int lda, const float* __restrict__ W,
    int K, int N, int m0, int n0, int tid, float acc[2][2][4])
{
    __shared__ float As[2][64][36];
    __shared__ float Bs[2][32][72];
    int warp = tid >> 5, lane = tid & 31;
    int wm = warp & 1, wn = warp >> 1;
    int g = lane >> 2, tg = lane & 3;

    auto issue = [&](int k0, int buf) {
        #pragma unroll
        for (int l = 0; l < 2; l++) {
            int idx = tid + l*256;
            int row = idx >> 3, kc = (idx & 7) * 4;
            cp_async16(&As[buf][row][kc], &A[(size_t)(m0+row)*lda + k0 + kc]);
        }
        #pragma unroll
        for (int l = 0; l < 2; l++) {
            int idx = tid + l*256;
            int kr = idx >> 4, nc = (idx & 15) * 4;
            cp_async16(&Bs[buf][kr][nc], &W[(size_t)(k0+kr)*N + n0 + nc]);
        }
        CP_COMMIT();
    };

    int nk = K / 32;
    issue(0, 0);
    int buf = 0;
    for (int it = 0; it < nk; it++) {
        bool more = (it + 1) < nk;
        if (more) issue((it+1)*32, buf^1);
        if (more) CP_WAIT1(); else CP_WAIT0();
        __syncthreads();

        #pragma unroll
        for (int kk = 0; kk < 32; kk += 8) {
            uint32_t ah[2][4], al[2][4], bh[2][2], bl[2][2];
            #pragma unroll
            for (int mt = 0; mt < 2; mt++) {
                int mrow = wm*32 + mt*16 + g;
                float a0 = As[buf][mrow  ][kk+tg];
                float a1 = As[buf][mrow+8][kk+tg];
                float a2 = As[buf][mrow  ][kk+tg+4];
                float a3 = As[buf][mrow+8][kk+tg+4];
                ah[mt][0] = f2tf32(a0); al[mt][0] = f2tf32(a0 - __uint_as_float(ah[mt][0]));
                ah[mt][1] = f2tf32(a1); al[mt][1] = f2tf32(a1 - __uint_as_float(ah[mt][1]));
                ah[mt][2] = f2tf32(a2); al[mt][2] = f2tf32(a2 - __uint_as_float(ah[mt][2]));
                ah[mt][3] = f2tf32(a3); al[mt][3] = f2tf32(a3 - __uint_as_float(ah[mt][3]));
            }
            #pragma unroll
            for (int nt = 0; nt < 2; nt++) {
                int ncol = wn*16 + nt*8 + g;
                float b0 = Bs[buf][kk+tg  ][ncol];
                float b1 = Bs[buf][kk+tg+4][ncol];
                bh[nt][0] = f2tf32(b0); bl[nt][0] = f2tf32(b0 - __uint_as_float(bh[nt][0]));
                bh[nt][1] = f2tf32(b1); bl[nt][1] = f2tf32(b1 - __uint_as_float(bh[nt][1]));
            }
            #pragma unroll
            for (int mt = 0; mt < 2; mt++)
                #pragma unroll
                for (int nt = 0; nt < 2; nt++) {
                    mma_tf32(acc[mt][nt], ah[mt][0], ah[mt][1], ah[mt][2], ah[mt][3],
                             bl[nt][0], bl[nt][1]);
                    mma_tf32(acc[mt][nt], al[mt][0], al[mt][1], al[mt][2], al[mt][3],
                             bh[nt][0], bh[nt][1]);
                    mma_tf32(acc[mt][nt], ah[mt][0], ah[mt][1], ah[mt][2], ah[mt][3],
                             bh[nt][0], bh[nt][1]);
                }
        }
        __syncthreads();
        buf ^= 1;
    }
}

// shared epilogue for 64x64 tc tiles
__device__ __forceinline__ void tc64_epilogue(
    float acc[2][2][4], const float* __restrict__ res, float* __restrict__ Out,
    int N, int m0, int n0, int tid, int epi)
{
    int warp = tid >> 5, lane = tid & 31;
    int wm = warp & 1, wn = warp >> 1;
    int g = lane >> 2, tg = lane & 3;
    #pragma unroll
    for (int mt = 0; mt < 2; mt++) {
        #pragma unroll
        for (int nt = 0; nt < 2; nt++) {
            int row = m0 + wm*32 + mt*16 + g;
            int col = n0 + wn*16 + nt*8 + 2*tg;
            float2 lo = { acc[mt][nt][0], acc[mt][nt][1] };
            float2 hi = { acc[mt][nt][2], acc[mt][nt][3] };
            if (epi == 1) {
                float2 r0 = *(const float2*)&res[(size_t)row*N + col];
                float2 r1 = *(const float2*)&res[(size_t)(row+8)*N + col];
                lo.x += r0.x; lo.y += r0.y;
                hi.x += r1.x; hi.y += r1.y;
            } else if (epi == 2) {
                lo.x = lo.x / (1.f + expf(-lo.x));
                lo.y = lo.y / (1.f + expf(-lo.y));
                hi.x = hi.x / (1.f + expf(-hi.x));
                hi.y = hi.y / (1.f + expf(-hi.y));
            }
            *(float2*)&Out[(size_t)row*N + col]     = lo;
            *(float2*)&Out[(size_t)(row+8)*N + col] = hi;
        }
    }
}

// ---------------- mid GEMM, direct (used for W1) ----------------
__global__ void __launch_bounds__(256) gemm_mid_tc(
    const float* __restrict__ A, const float* __restrict__ Wb,
    const float* __restrict__ res, float* __restrict__ Out,
    const int* __restrict__ cur, int K, int N, int epi)
{
    int m0 = blockIdx.y*64, n0 = blockIdx.x*64;
    const float* W = Wb;
    if (cur) W += (size_t)cur[m0 / Ss] * K * N;
    float acc[2][2][4] = {};
    tc64_core(A, K, W, K, N, m0, n0, threadIdx.x, acc);
    tc64_epilogue(acc, res, Out, N, m0, n0, threadIdx.x, epi);
}

// ---------------- split-K mid GEMM -> partials (N = Dd) ----------------
__global__ void __launch_bounds__(256) gemm_sk(
    const float* __restrict__ A, const float* __restrict__ Wb,
    float* __restrict__ part, const int* __restrict__ cur, int Kfull, int klen)
{
    int m0 = blockIdx.y*64, n0 = blockIdx.x*64;
    int z = blockIdx.z;
    const float* W = Wb + (size_t)cur[m0 / Ss] * Kfull * Dd + (size_t)z * klen * Dd;
    float acc[2][2][4] = {};
    tc64_core(A + (size_t)z * klen, Kfull, W, klen, Dd, m0, n0, threadIdx.x, acc);
    tc64_epilogue(acc, nullptr, part + (size_t)z * TOK * Dd, Dd, m0, n0, threadIdx.x, 0);
}

// ---------------- split-K QKV -> 6 partials ----------------
__global__ void __launch_bounds__(256) qkv_sk(
    const float* __restrict__ xn,
    const float* __restrict__ Wq, const float* __restrict__ Wk, const float* __restrict__ Wv,
    float* __restrict__ part, const int* __restrict__ cur)
{
    int z = blockIdx.z;
    int op = z >> 1, half = z & 1;
    const float* Wb = (op == 0) ? Wq : (op == 1) ? Wk : Wv;
    int m0 = blockIdx.y*64, n0 = blockIdx.x*64;
    const float* W = Wb + (size_t)cur[m0 / Ss] * Dd * Dd + (size_t)half * 256 * Dd;
    float acc[2][2][4] = {};
    tc64_core(xn + (size_t)half * 256, Dd, W, 256, Dd, m0, n0, threadIdx.x, acc);
    tc64_epilogue(acc, nullptr, part + (size_t)z * TOK * Dd, Dd, m0, n0, threadIdx.x, 0);
}

// ---------------- fused qkv reduce (2 partials each) + rope ----------------
__global__ void qkvrope_k(const float* __restrict__ part,
                          float* __restrict__ q, float* __restrict__ k, float* __restrict__ v) {
    int t = blockIdx.x;
    int s = t % Ss;
    int i = threadIdx.x;
    int base = t*Dd + 2*i;
    float q0=0, q1=0, k0=0, k1=0, v0=0, v1=0;
    #pragma unroll
    for (int z = 0; z < 2; z++) {
        const float* pq = part + (size_t)z      * TOK*Dd + base;
        const float* pk = part + (size_t)(2+z)  * TOK*Dd + base;
        const float* pv = part + (size_t)(4+z)  * TOK*Dd + base;
        q0 += pq[0]; q1 += pq[1];
        k0 += pk[0]; k1 += pk[1];
        v0 += pv[0]; v1 += pv[1];
    }
    int j = i & 31;
    float inv = powf(10000.f, -(2.f*j) / 64.f);
    float ang = (float)s * inv;
    float c = cosf(ang), sn = sinf(ang);
    q[base]   = q0*c - q1*sn;
    q[base+1] = q0*sn + q1*c;
    k[base]   = k0*c - k1*sn;
    k[base+1] = k0*sn + k1*c;
    v[base]   = v0;
    v[base+1] = v1;
}

// ---------------- fused Wo reduce (2 partials) + residual + rmsnorm(n2) ------
__global__ void rednorm_k(float* __restrict__ x, const float* __restrict__ part,
                          const float* __restrict__ w, const int* __restrict__ cur,
                          float* __restrict__ out) {
    int t = blockIdx.x;
    int d = threadIdx.x;          // 512
    __shared__ float red[512];
    int idx = t*Dd + d;
    float v = x[idx];
    #pragma unroll
    for (int z = 0; z < 2; z++) v += part[(size_t)z*TOK*Dd + idx];
    x[idx] = v;
    red[d] = v*v;
    __syncthreads();
    for (int s = 256; s > 0; s >>= 1) {
        if (d < s) red[d] += red[d+s];
        __syncthreads();
    }
    float scale = rsqrtf(red[0] * (1.0f/Dd) + 1e-6f);
    out[idx] = v * scale * w[(size_t)cur[t / Ss] * Dd + d];
}

// ---------------- reduce: x += sum of S partials ----------------
__global__ void red_add(float* __restrict__ x, const float* __restrict__ part, int S) {
    int i = blockIdx.x*256 + threadIdx.x;
    float s = x[i];
    for (int j = 0; j < S; j++) s += part[(size_t)j*TOK*Dd + i];
    x[i] = s;
}

// ---------------- flash attention: block per (b, h, q-tile of 64) ----------------
// 256 threads = 64 q-rows x 4 subs. Online softmax. smem: Qs,Ks,Vs,Ps [64][68].
#define ATT_SMEM (4*64*68*(int)sizeof(float))
__global__ void __launch_bounds__(256) fattn_k(
    const float* __restrict__ q, const float* __restrict__ k,
    const float* __restrict__ v, float* __restrict__ o)
{
    extern __shared__ float asm_[];
    float (*Qs)[68] = (float(*)[68])asm_;
    float (*Ks)[68] = (float(*)[68])(asm_ + 64*68);
    float (*Vs)[68] = (float(*)[68])(asm_ + 2*64*68);
    float (*Ps)[68] = (float(*)[68])(asm_ + 3*64*68);
    int qt = blockIdx.x, h = blockIdx.y, b = blockIdx.z;
    int tid = threadIdx.x;
    int row = tid >> 2;           // q row in tile, 0..63
    int sub = tid & 3;            // 0..3
    int base_bh = b*Ss*Dd + h*HD;
    int gq = qt*64 + row;

    // load Q tile (64 x 64), coalesced float4
    #pragma unroll
    for (int l = 0; l < 4; l++) {
        int idx = tid + l*256;
        int r = idx >> 4;
        int c = (idx & 15) * 4;
        *(float4*)&Qs[r][c] = *(const float4*)&q[base_bh + (qt*64 + r)*Dd + c];
    }

    float m = -1e30f, lsum = 0.f;
    float Oacc[16];
    #pragma unroll
    for (int t = 0; t < 16; t++) Oacc[t] = 0.f;
    int dg = sub*16;

    for (int kt = 0; kt <= qt; kt++) {
        __syncthreads();          // Q loaded; prev-iter Vs/Ps consumers done
        #pragma unroll
        for (int l = 0; l < 4; l++) {
            int idx = tid + l*256;
            int r = idx >> 4;
            int c = (idx & 15) * 4;
            *(float4*)&Ks[r][c] = *(const float4*)&k[base_bh + (kt*64 + r)*Dd + c];
            *(float4*)&Vs[r][c] = *(const float4*)&v[base_bh + (kt*64 + r)*Dd + c];
        }
        __syncthreads();

        // scores: this thread handles j = sub + jj*4 (bank-stagger)
        float s[16];
        #pragma unroll
        for (int jj = 0; jj < 16; jj++) s[jj] = 0.f;
        for (int d = 0; d < HD; d++) {
            float qd = Qs[row][d];
            #pragma unroll
            for (int jj = 0; jj < 16; jj++)
                s[jj] = fmaf(qd, Ks[sub + jj*4][d], s[jj]);
        }
        int kbase = kt*64;
        float mt_ = -1e30f;
        #pragma unroll
        for (int jj = 0; jj < 16; jj++) {
            int jg = kbase + sub + jj*4;
            s[jj] = (jg <= gq) ? s[jj]*0.125f : -1e30f;
            mt_ = fmaxf(mt_, s[jj]);
        }
        mt_ = fmaxf(mt_, __shfl_xor_sync(0xffffffffu, mt_, 1));
        mt_ = fmaxf(mt_, __shfl_xor_sync(0xffffffffu, mt_, 2));
        float m_new = fmaxf(m, mt_);
        float factor = expf(m - m_new);
        float lt = 0.f;
        #pragma unroll
        for (int jj = 0; jj < 16; jj++) {
            float p = expf(s[jj] - m_new);
            Ps[row][sub + jj*4] = p;
            lt += p;
        }
        lt += __shfl_xor_sync(0xffffffffu, lt, 1);
        lt += __shfl_xor_sync(0xffffffffu, lt, 2);
        lsum = lsum * factor + lt;
        m = m_new;
        #pragma unroll
        for (int t = 0; t < 16; t++) Oacc[t] *= factor;
        __syncthreads();

        // O accumulation: thread handles (row, d = dg..dg+15)
        for (int j = 0; j < 64; j++) {
            float pj = Ps[row][j];
            #pragma unroll
            for (int t = 0; t < 16; t++)
                Oacc[t] = fmaf(pj, Vs[j][dg + t], Oacc[t]);
        }
    }

    float inv = 1.f / lsum;
    float4 o4;
    #pragma unroll
    for (int u = 0; u < 4; u++) {
        o4.x = Oacc[u*4+0]*inv; o4.y = Oacc[u*4+1]*inv;
        o4.z = Oacc[u*4+2]*inv; o4.w = Oacc[u*4+3]*inv;
        *(float4*)&o[base_bh + (size_t)gq*Dd + dg + u*4] = o4;
    }
}

// ---------------- parallel pooling ----------------
__global__ void pool_k(const float* __restrict__ x, float* __restrict__ pooled) {
    int b = blockIdx.y;
    int d = blockIdx.x*128 + threadIdx.x;
    float s = 0.f;
    #pragma unroll 4
    for (int ss = 0; ss < Ss; ss++) s += x[(size_t)(b*Ss+ss)*Dd + d];
    pooled[b*Dd + d] = s * (1.f/Ss);
}

// ---------------- gating + routing (single block, reads pooled) ----------------
__global__ void gate_k(const float* __restrict__ pooled, const float* __restrict__ gw) {
    __shared__ float red[512];
    __shared__ float sc[2*(Cc+1)];
    int tid = threadIdx.x;
    for (int idx = 0; idx < 2*(Cc+1); idx++) {
        int b = idx / (Cc+1), c = idx % (Cc+1);
        red[tid] = pooled[b*Dd + tid] * gw[tid*(Cc+1) + c];
        __syncthreads();
        for (int s = 256; s > 0; s >>= 1) {
            if (tid < s) red[tid] += red[tid+s];
            __syncthreads();
        }
        if (tid == 0) sc[idx] = red[0];
        __syncthreads();
    }
    if (tid == 0) {
        float p[Bb][Cc+1];
        for (int b = 0; b < Bb; b++) {
            float mx = -1e30f;
            for (int c = 0; c < Cc+1; c++) mx = fmaxf(mx, sc[b*(Cc+1)+c]);
            float sum = 0.f;
            for (int c = 0; c < Cc+1; c++) { p[b][c] = expf(sc[b*(Cc+1)+c] - mx); sum += p[b][c]; }
            for (int c = 0; c < Cc+1; c++) p[b][c] /= sum;
        }
        float lb = 0.f;
        for (int c = 0; c < Cc+1; c++) {
            g_accp[c] += p[0][c] + p[1][c];
            float avg = 0.5f * (p[0][c] + p[1][c]);
            lb += avg*avg;
        }
        g_acclb += (float)(Cc+1) * lb;
        for (int b = 0; b < Bb; b++) {
            int co = g_cur[b];
            int j1 = (co+1) & 3, j2 = (co+2) & 3;
            float s1 = sc[b*(Cc+1)+j1], s2 = sc[b*(Cc+1)+j2];
            int w;
            if (s1 > s2) w = j1;
            else if (s2 > s1) w = j2;
            else w = (j1 < j2) ? j1 : j2;
            g_cur[b] = w;
        }
    }
}

// ---------------- host orchestration ----------------
extern "C" void kernel_launch(void* const* d_in, const int* in_sizes, int n_in,
                              void* d_out, int out_size) {
    const int*   ids   = (const int*)  d_in[0];
    const int*   start = (const int*)  d_in[1];
    const float* emb   = (const float*)d_in[2];
    const float* Wq    = (const float*)d_in[3];
    const float* Wk    = (const float*)d_in[4];
    const float* Wv    = (const float*)d_in[5];
    const float* Wo    = (const float*)d_in[6];
    const float* W1    = (const float*)d_in[7];
    const float* W2    = (const float*)d_in[8];
    const float* n1    = (const float*)d_in[9];
    const float* n2    = (const float*)d_in[10];
    const float* gw    = (const float*)d_in[11];
    const float* fnw   = (const float*)d_in[12];
    const float* fcw   = (const float*)d_in[13];
    float* out = (float*)d_out;

    float *x, *xn, *q, *k, *v, *o, *ff, *part, *pool;
    int* cur;
    cudaGetSymbolAddress((void**)&x,  g_x);
    cudaGetSymbolAddress((void**)&xn, g_xn);
    cudaGetSymbolAddress((void**)&q,  g_q);
    cudaGetSymbolAddress((void**)&k,  g_k);
    cudaGetSymbolAddress((void**)&v,  g_v);
    cudaGetSymbolAddress((void**)&o,  g_o);
    cudaGetSymbolAddress((void**)&ff, g_ff);
    cudaGetSymbolAddress((void**)&part, g_part);
    cudaGetSymbolAddress((void**)&pool, g_pool);
    cudaGetSymbolAddress((void**)&cur, g_cur);

    static int smem_set = 0;
    if (!smem_set) {
        cudaFuncSetAttribute(gemm_tc, cudaFuncAttributeMaxDynamicSharedMemorySize, TC_SMEM);
        cudaFuncSetAttribute(fattn_k, cudaFuncAttributeMaxDynamicSharedMemorySize, ATT_SMEM);
        smem_set = 1;
    }

    embednorm_k<<<TOK, Dd>>>(ids, start, emb, n1, x, xn);

    int nred = TOK*Dd/256;            // 1024 blocks
    dim3 gqkv(Dd/64, TOK/64, 6);      // 384 blocks (split-K=2 x q,k,v)
    dim3 gwo (Dd/64, TOK/64, 2);      // 128 blocks (split-K=2)
    dim3 gw1 (Ff/64, TOK/64);         // 256 blocks
    dim3 gw2 (Dd/64, TOK/64, 4);      // 256 blocks (split-K=4)
    dim3 gatt(Ss/64, Hh, Bb);         // 64 blocks
    for (int step = 0; step < 2; step++) {
        if (step > 0)
            rmsnorm_k<<<TOK, Dd>>>(x, n1, cur, xn);
        qkv_sk<<<gqkv, 256>>>(xn, Wq, Wk, Wv, part, cur);
        qkvrope_k<<<TOK, 256>>>(part, q, k, v);
        fattn_k<<<gatt, 256, ATT_SMEM>>>(q, k, v, o);
        gemm_sk<<<gwo, 256>>>(o, Wo, part, cur, Dd, 256);
        rednorm_k<<<TOK, Dd>>>(x, part, n2, cur, xn);
        gemm_mid_tc<<<gw1, 256>>>(xn, W1, nullptr, ff, cur, Dd, Ff, 2);
        gemm_sk<<<gw2, 256>>>(ff, W2, part, cur, Ff, 512);
        red_add<<<nred, 256>>>(x, part, 4);
        pool_k<<<dim3(Dd/128, Bb), 128>>>(x, pool);
        gate_k<<<1, 512>>>(pool, gw);
    }
    rmsnorm_k<<<TOK, Dd>>>(x, fnw, nullptr, xn);
    gemm_tc<<<dim3(TOK/128, Vv/128), 256, TC_SMEM>>>(xn, fcw, out, Dd, Vv, out_size);
}

// round 11
// speedup vs baseline: 2.6874x; 1.1571x over previous
#include <cuda_runtime.h>
#include <math.h>
#include <stdint.h>

#define Dd  512
#define Hh  8
#define HD  64
#define Bb  2
#define Ss  256
#define Ff  2048
#define Cc  4
#define Vv  32000
#define TOK (Bb*Ss)   // 512

// ---------------- device state (no allocation allowed) ----------------
__device__ float g_x [TOK*Dd];
__device__ float g_xn[TOK*Dd];
__device__ float g_q [TOK*Dd];
__device__ float g_k [TOK*Dd];
__device__ float g_v [TOK*Dd];
__device__ float g_o [TOK*Dd];
__device__ float g_ff[TOK*Ff];
__device__ float g_part[6*TOK*Dd];
__device__ float g_pool[Bb*Dd];
__device__ int   g_cur[Bb];
__device__ float g_accp[Cc+1];
__device__ float g_acclb;

// ---------------- fused embed + init + first rmsnorm (cur = start) ----------------
__global__ void embednorm_k(const int* __restrict__ ids, const int* __restrict__ start,
                            const float* __restrict__ emb, const float* __restrict__ n1,
                            float* __restrict__ x, float* __restrict__ out) {
    int t = blockIdx.x;
    int d = threadIdx.x;          // 512
    __shared__ float red[512];
    if (t == 0 && d == 0) {
        g_cur[0] = start[0];
        g_cur[1] = start[1];
        #pragma unroll
        for (int i = 0; i < Cc+1; i++) g_accp[i] = 0.f;
        g_acclb = 0.f;
    }
    float v = emb[(size_t)ids[t]*Dd + d] * sqrtf((float)Dd);
    x[t*Dd + d] = v;
    red[d] = v*v;
    __syncthreads();
    for (int s = 256; s > 0; s >>= 1) {
        if (d < s) red[d] += red[d+s];
        __syncthreads();
    }
    float scale = rsqrtf(red[0] * (1.0f/Dd) + 1e-6f);
    out[t*Dd + d] = v * scale * n1[(size_t)start[t / Ss] * Dd + d];
}

// ---------------- rmsnorm (block per token) ----------------
__global__ void rmsnorm_k(const float* __restrict__ x, const float* __restrict__ w,
                          const int* __restrict__ cur, float* __restrict__ out) {
    int t = blockIdx.x;
    int d = threadIdx.x;          // 512
    __shared__ float red[512];
    float v = x[t*Dd + d];
    red[d] = v*v;
    __syncthreads();
    for (int s = 256; s > 0; s >>= 1) {
        if (d < s) red[d] += red[d+s];
        __syncthreads();
    }
    float scale = rsqrtf(red[0] * (1.0f/Dd) + 1e-6f);
    const float* ww = w;
    if (cur) ww += (size_t)cur[t / Ss] * Dd;
    out[t*Dd + d] = v * scale * ww[d];
}

// ---------------- tf32 / cp.async helpers ----------------
__device__ __forceinline__ uint32_t f2tf32(float f) {
    uint32_t u;
    asm volatile("cvt.rna.tf32.f32 %0, %1;" : "=r"(u) : "f"(f));
    return u;
}

__device__ __forceinline__ void mma_tf32(float c[4],
    uint32_t a0, uint32_t a1, uint32_t a2, uint32_t a3,
    uint32_t b0, uint32_t b1)
{
    asm volatile(
        "mma.sync.aligned.m16n8k8.row.col.f32.tf32.tf32.f32 "
        "{%0,%1,%2,%3}, {%4,%5,%6,%7}, {%8,%9}, {%0,%1,%2,%3};"
        : "+f"(c[0]), "+f"(c[1]), "+f"(c[2]), "+f"(c[3])
        : "r"(a0), "r"(a1), "r"(a2), "r"(a3), "r"(b0), "r"(b1));
}

__device__ __forceinline__ void cp_async16(float* smem, const float* gmem) {
    uint32_t s;
    asm("{ .reg .u64 t; cvta.to.shared.u64 t, %1; cvt.u32.u64 %0, t; }"
        : "=r"(s) : "l"(smem));
    asm volatile("cp.async.cg.shared.global [%0], [%1], 16;" :: "r"(s), "l"(gmem) : "memory");
}
#define CP_COMMIT()  asm volatile("cp.async.commit_group;" ::: "memory")
#define CP_WAIT1()   asm volatile("cp.async.wait_group 1;" ::: "memory")
#define CP_WAIT0()   asm volatile("cp.async.wait_group 0;" ::: "memory")

// ---------------- tensor-core logits GEMM (verified) + fused aux write ------
#define TC_SMEM ((2*128*36 + 2*32*136) * (int)sizeof(float))
__global__ void __launch_bounds__(256,2) gemm_tc(
    const float* __restrict__ A, const float* __restrict__ W,
    float* __restrict__ Out, int K, int N, int aux_n)
{
    extern __shared__ float dsm[];
    float (*As)[128][36]  = (float(*)[128][36])dsm;
    float (*Bs)[32][136]  = (float(*)[32][136])(dsm + 2*128*36);
    int tid = threadIdx.x;
    int m0 = blockIdx.x*128, n0 = blockIdx.y*128;
    int warp = tid >> 5, lane = tid & 31;
    int wm = warp & 1, wn = warp >> 1;
    int g = lane >> 2, tg = lane & 3;

    if (blockIdx.x == 0 && blockIdx.y == 0 && tid == 0 && aux_n > 0) {
        float avg[Cc+1];
        float m = 0.f;
        #pragma unroll
        for (int i = 0; i < Cc+1; i++) { avg[i] = g_accp[i] * 0.25f; m += avg[i]; }
        m *= 1.f/(Cc+1);
        float var = 0.f;
        #pragma unroll
        for (int i = 0; i < Cc+1; i++) { float d = avg[i] - m; var += d*d; }
        var *= 1.f/(Cc+1);
        Out[aux_n-2] = var;
        Out[aux_n-1] = g_acclb * 0.5f;
    }

    auto issue = [&](int k0, int buf) {
        #pragma unroll
        for (int l = 0; l < 4; l++) {
            int idx = tid + l*256;
            int row = idx >> 3, kc = (idx & 7) * 4;
            cp_async16(&As[buf][row][kc], &A[(size_t)(m0+row)*K + k0 + kc]);
        }
        #pragma unroll
        for (int l = 0; l < 4; l++) {
            int idx = tid + l*256;
            int kr = idx >> 5, nc = (idx & 31) * 4;
            cp_async16(&Bs[buf][kr][nc], &W[(size_t)(k0+kr)*N + n0 + nc]);
        }
        CP_COMMIT();
    };

    float acc[4][4][4] = {};
    int nk = K / 32;
    issue(0, 0);
    int buf = 0;
    for (int it = 0; it < nk; it++) {
        bool more = (it + 1) < nk;
        if (more) issue((it+1)*32, buf^1);
        if (more) CP_WAIT1(); else CP_WAIT0();
        __syncthreads();

        #pragma unroll
        for (int kk = 0; kk < 32; kk += 8) {
            uint32_t af[4][4], bf[4][2];
            #pragma unroll
            for (int mt = 0; mt < 4; mt++) {
                int mrow = wm*64 + mt*16 + g;
                af[mt][0] = f2tf32(As[buf][mrow  ][kk+tg]);
                af[mt][1] = f2tf32(As[buf][mrow+8][kk+tg]);
                af[mt][2] = f2tf32(As[buf][mrow  ][kk+tg+4]);
                af[mt][3] = f2tf32(As[buf][mrow+8][kk+tg+4]);
            }
            #pragma unroll
            for (int nt = 0; nt < 4; nt++) {
                int ncol = wn*32 + nt*8 + g;
                bf[nt][0] = f2tf32(Bs[buf][kk+tg  ][ncol]);
                bf[nt][1] = f2tf32(Bs[buf][kk+tg+4][ncol]);
            }
            #pragma unroll
            for (int mt = 0; mt < 4; mt++)
                #pragma unroll
                for (int nt = 0; nt < 4; nt++)
                    mma_tf32(acc[mt][nt], af[mt][0], af[mt][1], af[mt][2], af[mt][3],
                             bf[nt][0], bf[nt][1]);
        }
        __syncthreads();
        buf ^= 1;
    }

    #pragma unroll
    for (int mt = 0; mt < 4; mt++) {
        #pragma unroll
        for (int nt = 0; nt < 4; nt++) {
            int row = m0 + wm*64 + mt*16 + g;
            int col = n0 + wn*32 + nt*8 + 2*tg;
            float2 lo = { acc[mt][nt][0], acc[mt][nt][1] };
            float2 hi = { acc[mt][nt][2], acc[mt][nt][3] };
            *(float2*)&Out[(size_t)row*N + col]     = lo;
            *(float2*)&Out[(size_t)(row+8)*N + col] = hi;
        }
    }
}

// ---------------- tf32x3 mid GEMM core (verified R7) ----------------
__device__ __forceinline__ void tc64_core(
    const float* __restrict__ A, int lda, const float* __restrict__ W,
    int K, int N, int m0, int n0, int tid, float acc[2][2][4])
{
    __shared__ float As[2][64][36];
    __shared__ float Bs[2][32][72];
    int warp = tid >> 5, lane = tid & 31;
    int wm = warp & 1, wn = warp >> 1;
    int g = lane >> 2, tg = lane & 3;

    auto issue = [&](int k0, int buf) {
        #pragma unroll
        for (int l = 0; l < 2; l++) {
            int idx = tid + l*256;
            int row = idx >> 3, kc = (idx & 7) * 4;
            cp_async16(&As[buf][row][kc], &A[(size_t)(m0+row)*lda + k0 + kc]);
        }
        #pragma unroll
        for (int l = 0; l < 2; l++) {
            int idx = tid + l*256;
            int kr = idx >> 4, nc = (idx & 15) * 4;
            cp_async16(&Bs[buf][kr][nc], &W[(size_t)(k0+kr)*N + n0 + nc]);
        }
        CP_COMMIT();
    };

    int nk = K / 32;
    issue(0, 0);
    int buf = 0;
    for (int it = 0; it < nk; it++) {
        bool more = (it + 1) < nk;
        if (more) issue((it+1)*32, buf^1);
        if (more) CP_WAIT1(); else CP_WAIT0();
        __syncthreads();

        #pragma unroll
        for (int kk = 0; kk < 32; kk += 8) {
            uint32_t ah[2][4], al[2][4], bh[2][2], bl[2][2];
            #pragma unroll
            for (int mt = 0; mt < 2; mt++) {
                int mrow = wm*32 + mt*16 + g;
                float a0 = As[buf][mrow  ][kk+tg];
                float a1 = As[buf][mrow+8][kk+tg];
                float a2 = As[buf][mrow  ][kk+tg+4];
                float a3 = As[buf][mrow+8][kk+tg+4];
                ah[mt][0] = f2tf32(a0); al[mt][0] = f2tf32(a0 - __uint_as_float(ah[mt][0]));
                ah[mt][1] = f2tf32(a1); al[mt][1] = f2tf32(a1 - __uint_as_float(ah[mt][1]));
                ah[mt][2] = f2tf32(a2); al[mt][2] = f2tf32(a2 - __uint_as_float(ah[mt][2]));
                ah[mt][3] = f2tf32(a3); al[mt][3] = f2tf32(a3 - __uint_as_float(ah[mt][3]));
            }
            #pragma unroll
            for (int nt = 0; nt < 2; nt++) {
                int ncol = wn*16 + nt*8 + g;
                float b0 = Bs[buf][kk+tg  ][ncol];
                float b1 = Bs[buf][kk+tg+4][ncol];
                bh[nt][0] = f2tf32(b0); bl[nt][0] = f2tf32(b0 - __uint_as_float(bh[nt][0]));
                bh[nt][1] = f2tf32(b1); bl[nt][1] = f2tf32(b1 - __uint_as_float(bh[nt][1]));
            }
            #pragma unroll
            for (int mt = 0; mt < 2; mt++)
                #pragma unroll
                for (int nt = 0; nt < 2; nt++) {
                    mma_tf32(acc[mt][nt], ah[mt][0], ah[mt][1], ah[mt][2], ah[mt][3],
                             bl[nt][0], bl[nt][1]);
                    mma_tf32(acc[mt][nt], al[mt][0], al[mt][1], al[mt][2], al[mt][3],
                             bh[nt][0], bh[nt][1]);
                    mma_tf32(acc[mt][nt], ah[mt][0], ah[mt][1], ah[mt][2], ah[mt][3],
                             bh[nt][0], bh[nt][1]);
                }
        }
        __syncthreads();
        buf ^= 1;
    }
}

// shared epilogue for 64x64 tc tiles
__device__ __forceinline__ void tc64_epilogue(
    float acc[2][2][4], const float* __restrict__ res, float* __restrict__ Out,
    int N, int m0, int n0, int tid, int epi)
{
    int warp = tid >> 5, lane = tid & 31;
    int wm = warp & 1, wn = warp >> 1;
    int g = lane >> 2, tg = lane & 3;
    #pragma unroll
    for (int mt = 0; mt < 2; mt++) {
        #pragma unroll
        for (int nt = 0; nt < 2; nt++) {
            int row = m0 + wm*32 + mt*16 + g;
            int col = n0 + wn*16 + nt*8 + 2*tg;
            float2 lo = { acc[mt][nt][0], acc[mt][nt][1] };
            float2 hi = { acc[mt][nt][2], acc[mt][nt][3] };
            if (epi == 1) {
                float2 r0 = *(const float2*)&res[(size_t)row*N + col];
                float2 r1 = *(const float2*)&res[(size_t)(row+8)*N + col];
                lo.x += r0.x; lo.y += r0.y;
                hi.x += r1.x; hi.y += r1.y;
            } else if (epi == 2) {
                lo.x = lo.x / (1.f + expf(-lo.x));
                lo.y = lo.y / (1.f + expf(-lo.y));
                hi.x = hi.x / (1.f + expf(-hi.x));
                hi.y = hi.y / (1.f + expf(-hi.y));
            }
            *(float2*)&Out[(size_t)row*N + col]     = lo;
            *(float2*)&Out[(size_t)(row+8)*N + col] = hi;
        }
    }
}

// ---------------- mid GEMM, direct (used for W1) ----------------
__global__ void __launch_bounds__(256) gemm_mid_tc(
    const float* __restrict__ A, const float* __restrict__ Wb,
    const float* __restrict__ res, float* __restrict__ Out,
    const int* __restrict__ cur, int K, int N, int epi)
{
    int m0 = blockIdx.y*64, n0 = blockIdx.x*64;
    const float* W = Wb;
    if (cur) W += (size_t)cur[m0 / Ss] * K * N;
    float acc[2][2][4] = {};
    tc64_core(A, K, W, K, N, m0, n0, threadIdx.x, acc);
    tc64_epilogue(acc, res, Out, N, m0, n0, threadIdx.x, epi);
}

// ---------------- split-K mid GEMM -> partials (N = Dd) ----------------
__global__ void __launch_bounds__(256) gemm_sk(
    const float* __restrict__ A, const float* __restrict__ Wb,
    float* __restrict__ part, const int* __restrict__ cur, int Kfull, int klen)
{
    int m0 = blockIdx.y*64, n0 = blockIdx.x*64;
    int z = blockIdx.z;
    const float* W = Wb + (size_t)cur[m0 / Ss] * Kfull * Dd + (size_t)z * klen * Dd;
    float acc[2][2][4] = {};
    tc64_core(A + (size_t)z * klen, Kfull, W, klen, Dd, m0, n0, threadIdx.x, acc);
    tc64_epilogue(acc, nullptr, part + (size_t)z * TOK * Dd, Dd, m0, n0, threadIdx.x, 0);
}

// ---------------- split-K QKV -> 6 partials ----------------
__global__ void __launch_bounds__(256) qkv_sk(
    const float* __restrict__ xn,
    const float* __restrict__ Wq, const float* __restrict__ Wk, const float* __restrict__ Wv,
    float* __restrict__ part, const int* __restrict__ cur)
{
    int z = blockIdx.z;
    int op = z >> 1, half = z & 1;
    const float* Wb = (op == 0) ? Wq : (op == 1) ? Wk : Wv;
    int m0 = blockIdx.y*64, n0 = blockIdx.x*64;
    const float* W = Wb + (size_t)cur[m0 / Ss] * Dd * Dd + (size_t)half * 256 * Dd;
    float acc[2][2][4] = {};
    tc64_core(xn + (size_t)half * 256, Dd, W, 256, Dd, m0, n0, threadIdx.x, acc);
    tc64_epilogue(acc, nullptr, part + (size_t)z * TOK * Dd, Dd, m0, n0, threadIdx.x, 0);
}

// ---------------- fused qkv reduce (2 partials each) + rope ----------------
__global__ void qkvrope_k(const float* __restrict__ part,
                          float* __restrict__ q, float* __restrict__ k, float* __restrict__ v) {
    int t = blockIdx.x;
    int s = t % Ss;
    int i = threadIdx.x;
    int base = t*Dd + 2*i;
    float q0=0, q1=0, k0=0, k1=0, v0=0, v1=0;
    #pragma unroll
    for (int z = 0; z < 2; z++) {
        const float* pq = part + (size_t)z      * TOK*Dd + base;
        const float* pk = part + (size_t)(2+z)  * TOK*Dd + base;
        const float* pv = part + (size_t)(4+z)  * TOK*Dd + base;
        q0 += pq[0]; q1 += pq[1];
        k0 += pk[0]; k1 += pk[1];
        v0 += pv[0]; v1 += pv[1];
    }
    int j = i & 31;
    float inv = powf(10000.f, -(2.f*j) / 64.f);
    float ang = (float)s * inv;
    float c = cosf(ang), sn = sinf(ang);
    q[base]   = q0*c - q1*sn;
    q[base+1] = q0*sn + q1*c;
    k[base]   = k0*c - k1*sn;
    k[base+1] = k0*sn + k1*c;
    v[base]   = v0;
    v[base+1] = v1;
}

// ---------------- fused Wo reduce (2 partials) + residual + rmsnorm(n2) ------
__global__ void rednorm_k(float* __restrict__ x, const float* __restrict__ part,
                          const float* __restrict__ w, const int* __restrict__ cur,
                          float* __restrict__ out) {
    int t = blockIdx.x;
    int d = threadIdx.x;          // 512
    __shared__ float red[512];
    int idx = t*Dd + d;
    float v = x[idx];
    #pragma unroll
    for (int z = 0; z < 2; z++) v += part[(size_t)z*TOK*Dd + idx];
    x[idx] = v;
    red[d] = v*v;
    __syncthreads();
    for (int s = 256; s > 0; s >>= 1) {
        if (d < s) red[d] += red[d+s];
        __syncthreads();
    }
    float scale = rsqrtf(red[0] * (1.0f/Dd) + 1e-6f);
    out[idx] = v * scale * w[(size_t)cur[t / Ss] * Dd + d];
}

// ---------------- reduce: x += sum of S partials ----------------
__global__ void red_add(float* __restrict__ x, const float* __restrict__ part, int S) {
    int i = blockIdx.x*256 + threadIdx.x;
    float s = x[i];
    for (int j = 0; j < S; j++) s += part[(size_t)j*TOK*Dd + i];
    x[i] = s;
}

// ---------------- flash attention v2: block per (b, h, q-tile of 32) ----------------
// 256 threads = 32 q-rows x 8 subs; k-tile 64; online softmax.
// smem: Qs[32][68], Ks[64][68], Vs[64][68], Ps[32][68] = 52224 B.
#define ATT_SMEM ((32*68 + 64*68 + 64*68 + 32*68) * (int)sizeof(float))
__global__ void __launch_bounds__(256,2) fattn_k(
    const float* __restrict__ q, const float* __restrict__ k,
    const float* __restrict__ v, float* __restrict__ o)
{
    extern __shared__ float asm_[];
    float (*Qs)[68] = (float(*)[68])asm_;
    float (*Ks)[68] = (float(*)[68])(asm_ + 32*68);
    float (*Vs)[68] = (float(*)[68])(asm_ + 32*68 + 64*68);
    float (*Ps)[68] = (float(*)[68])(asm_ + 32*68 + 2*64*68);
    int qt = blockIdx.x, h = blockIdx.y, b = blockIdx.z;
    int tid = threadIdx.x;
    int row = tid >> 3;           // q row in tile, 0..31
    int sub = tid & 7;            // 0..7
    int base_bh = b*Ss*Dd + h*HD;
    int gq = qt*32 + row;

    // load Q tile (32 x 64)
    #pragma unroll
    for (int l = 0; l < 2; l++) {
        int idx = tid + l*256;
        int r = idx >> 4;
        int c = (idx & 15) * 4;
        *(float4*)&Qs[r][c] = *(const float4*)&q[base_bh + (qt*32 + r)*Dd + c];
    }

    float m = -1e30f, lsum = 0.f;
    float Oacc[8];
    #pragma unroll
    for (int t = 0; t < 8; t++) Oacc[t] = 0.f;

    int nkt = qt/2 + 1;           // k-tiles of 64 covering causal range
    for (int kt = 0; kt < nkt; kt++) {
        __syncthreads();          // Q loaded / prev Vs consumers done
        #pragma unroll
        for (int l = 0; l < 4; l++) {
            int idx = tid + l*256;
            int r = idx >> 4;
            int c = (idx & 15) * 4;
            *(float4*)&Ks[r][c] = *(const float4*)&k[base_bh + (kt*64 + r)*Dd + c];
            *(float4*)&Vs[r][c] = *(const float4*)&v[base_bh + (kt*64 + r)*Dd + c];
        }
        __syncthreads();

        // scores: thread handles j = sub + jj*8 (8 distinct banks across subs)
        float s[8];
        #pragma unroll
        for (int jj = 0; jj < 8; jj++) s[jj] = 0.f;
        for (int d = 0; d < HD; d++) {
            float qd = Qs[row][d];
            #pragma unroll
            for (int jj = 0; jj < 8; jj++)
                s[jj] = fmaf(qd, Ks[sub + jj*8][d], s[jj]);
        }
        int kbase = kt*64;
        float mt_ = -1e30f;
        #pragma unroll
        for (int jj = 0; jj < 8; jj++) {
            int jg = kbase + sub + jj*8;
            s[jj] = (jg <= gq) ? s[jj]*0.125f : -1e30f;
            mt_ = fmaxf(mt_, s[jj]);
        }
        mt_ = fmaxf(mt_, __shfl_xor_sync(0xffffffffu, mt_, 1));
        mt_ = fmaxf(mt_, __shfl_xor_sync(0xffffffffu, mt_, 2));
        mt_ = fmaxf(mt_, __shfl_xor_sync(0xffffffffu, mt_, 4));
        float m_new = fmaxf(m, mt_);
        float factor = expf(m - m_new);
        float lt = 0.f;
        #pragma unroll
        for (int jj = 0; jj < 8; jj++) {
            float p = expf(s[jj] - m_new);
            Ps[row][sub + jj*8] = p;
            lt += p;
        }
        lt += __shfl_xor_sync(0xffffffffu, lt, 1);
        lt += __shfl_xor_sync(0xffffffffu, lt, 2);
        lt += __shfl_xor_sync(0xffffffffu, lt, 4);
        lsum = lsum * factor + lt;
        m = m_new;
        #pragma unroll
        for (int t = 0; t < 8; t++) Oacc[t] *= factor;
        __syncwarp();             // Ps row is produced/consumed within one warp

        // O accumulation: thread owns d = sub + 8t (conflict-free Vs reads)
        for (int j = 0; j < 64; j++) {
            float pj = Ps[row][j];
            #pragma unroll
            for (int t = 0; t < 8; t++)
                Oacc[t] = fmaf(pj, Vs[j][sub + 8*t], Oacc[t]);
        }
    }

    float inv = 1.f / lsum;
    #pragma unroll
    for (int t = 0; t < 8; t++)
        o[base_bh + (size_t)gq*Dd + sub + 8*t] = Oacc[t] * inv;
}

// ---------------- parallel pooling ----------------
__global__ void pool_k(const float* __restrict__ x, float* __restrict__ pooled) {
    int b = blockIdx.y;
    int d = blockIdx.x*128 + threadIdx.x;
    float s = 0.f;
    #pragma unroll 4
    for (int ss = 0; ss < Ss; ss++) s += x[(size_t)(b*Ss+ss)*Dd + d];
    pooled[b*Dd + d] = s * (1.f/Ss);
}

// ---------------- gating + routing (single block, reads pooled) ----------------
__global__ void gate_k(const float* __restrict__ pooled, const float* __restrict__ gw) {
    __shared__ float red[512];
    __shared__ float sc[2*(Cc+1)];
    int tid = threadIdx.x;
    for (int idx = 0; idx < 2*(Cc+1); idx++) {
        int b = idx / (Cc+1), c = idx % (Cc+1);
        red[tid] = pooled[b*Dd + tid] * gw[tid*(Cc+1) + c];
        __syncthreads();
        for (int s = 256; s > 0; s >>= 1) {
            if (tid < s) red[tid] += red[tid+s];
            __syncthreads();
        }
        if (tid == 0) sc[idx] = red[0];
        __syncthreads();
    }
    if (tid == 0) {
        float p[Bb][Cc+1];
        for (int b = 0; b < Bb; b++) {
            float mx = -1e30f;
            for (int c = 0; c < Cc+1; c++) mx = fmaxf(mx, sc[b*(Cc+1)+c]);
            float sum = 0.f;
            for (int c = 0; c < Cc+1; c++) { p[b][c] = expf(sc[b*(Cc+1)+c] - mx); sum += p[b][c]; }
            for (int c = 0; c < Cc+1; c++) p[b][c] /= sum;
        }
        float lb = 0.f;
        for (int c = 0; c < Cc+1; c++) {
            g_accp[c] += p[0][c] + p[1][c];
            float avg = 0.5f * (p[0][c] + p[1][c]);
            lb += avg*avg;
        }
        g_acclb += (float)(Cc+1) * lb;
        for (int b = 0; b < Bb; b++) {
            int co = g_cur[b];
            int j1 = (co+1) & 3, j2 = (co+2) & 3;
            float s1 = sc[b*(Cc+1)+j1], s2 = sc[b*(Cc+1)+j2];
            int w;
            if (s1 > s2) w = j1;
            else if (s2 > s1) w = j2;
            else w = (j1 < j2) ? j1 : j2;
            g_cur[b] = w;
        }
    }
}

// ---------------- host orchestration ----------------
extern "C" void kernel_launch(void* const* d_in, const int* in_sizes, int n_in,
                              void* d_out, int out_size) {
    const int*   ids   = (const int*)  d_in[0];
    const int*   start = (const int*)  d_in[1];
    const float* emb   = (const float*)d_in[2];
    const float* Wq    = (const float*)d_in[3];
    const float* Wk    = (const float*)d_in[4];
    const float* Wv    = (const float*)d_in[5];
    const float* Wo    = (const float*)d_in[6];
    const float* W1    = (const float*)d_in[7];
    const float* W2    = (const float*)d_in[8];
    const float* n1    = (const float*)d_in[9];
    const float* n2    = (const float*)d_in[10];
    const float* gw    = (const float*)d_in[11];
    const float* fnw   = (const float*)d_in[12];
    const float* fcw   = (const float*)d_in[13];
    float* out = (float*)d_out;

    float *x, *xn, *q, *k, *v, *o, *ff, *part, *pool;
    int* cur;
    cudaGetSymbolAddress((void**)&x,  g_x);
    cudaGetSymbolAddress((void**)&xn, g_xn);
    cudaGetSymbolAddress((void**)&q,  g_q);
    cudaGetSymbolAddress((void**)&k,  g_k);
    cudaGetSymbolAddress((void**)&v,  g_v);
    cudaGetSymbolAddress((void**)&o,  g_o);
    cudaGetSymbolAddress((void**)&ff, g_ff);
    cudaGetSymbolAddress((void**)&part, g_part);
    cudaGetSymbolAddress((void**)&pool, g_pool);
    cudaGetSymbolAddress((void**)&cur, g_cur);

    static int smem_set = 0;
    if (!smem_set) {
        cudaFuncSetAttribute(gemm_tc, cudaFuncAttributeMaxDynamicSharedMemorySize, TC_SMEM);
        cudaFuncSetAttribute(fattn_k, cudaFuncAttributeMaxDynamicSharedMemorySize, ATT_SMEM);
        smem_set = 1;
    }

    embednorm_k<<<TOK, Dd>>>(ids, start, emb, n1, x, xn);

    int nred = TOK*Dd/256;            // 1024 blocks
    dim3 gqkv(Dd/64, TOK/64, 6);      // 384 blocks (split-K=2 x q,k,v)
    dim3 gwo (Dd/64, TOK/64, 2);      // 128 blocks (split-K=2)
    dim3 gw1 (Ff/64, TOK/64);         // 256 blocks
    dim3 gw2 (Dd/64, TOK/64, 4);      // 256 blocks (split-K=4)
    dim3 gatt(Ss/32, Hh, Bb);         // 128 blocks
    for (int step = 0; step < 2; step++) {
        if (step > 0)
            rmsnorm_k<<<TOK, Dd>>>(x, n1, cur, xn);
        qkv_sk<<<gqkv, 256>>>(xn, Wq, Wk, Wv, part, cur);
        qkvrope_k<<<TOK, 256>>>(part, q, k, v);
        fattn_k<<<gatt, 256, ATT_SMEM>>>(q, k, v, o);
        gemm_sk<<<gwo, 256>>>(o, Wo, part, cur, Dd, 256);
        rednorm_k<<<TOK, Dd>>>(x, part, n2, cur, xn);
        gemm_mid_tc<<<gw1, 256>>>(xn, W1, nullptr, ff, cur, Dd, Ff, 2);
        gemm_sk<<<gw2, 256>>>(ff, W2, part, cur, Ff, 512);
        red_add<<<nred, 256>>>(x, part, 4);
        pool_k<<<dim3(Dd/128, Bb), 128>>>(x, pool);
        gate_k<<<1, 512>>>(pool, gw);
    }
    rmsnorm_k<<<TOK, Dd>>>(x, fnw, nullptr, xn);
    gemm_tc<<<dim3(TOK/128, Vv/128), 256, TC_SMEM>>>(xn, fcw, out, Dd, Vv, out_size);
}

// round 12
// speedup vs baseline: 2.8254x; 1.0514x over previous
#include <cuda_runtime.h>
#include <math.h>
#include <stdint.h>

#define Dd  512
#define Hh  8
#define HD  64
#define Bb  2
#define Ss  256
#define Ff  2048
#define Cc  4
#define Vv  32000
#define TOK (Bb*Ss)   // 512

// ---------------- device state (no allocation allowed) ----------------
__device__ float g_x  [TOK*Dd];
__device__ float g_xnh[TOK*Dd];
__device__ float g_xnl[TOK*Dd];
__device__ float g_q  [TOK*Dd];
__device__ float g_k  [TOK*Dd];
__device__ float g_v  [TOK*Dd];
__device__ float g_oh [TOK*Dd];
__device__ float g_ol [TOK*Dd];
__device__ float g_ffh[TOK*Ff];
__device__ float g_ffl[TOK*Ff];
__device__ float g_part[6*TOK*Dd];
__device__ float g_pool[Bb*Dd];
__device__ int   g_cur[Bb];
__device__ float g_accp[Cc+1];
__device__ float g_acclb;

// ---------------- tf32 / cp.async helpers ----------------
__device__ __forceinline__ uint32_t f2tf32(float f) {
    uint32_t u;
    asm volatile("cvt.rna.tf32.f32 %0, %1;" : "=r"(u) : "f"(f));
    return u;
}

__device__ __forceinline__ void split_store(float v, float* __restrict__ ph, float* __restrict__ pl) {
    uint32_t h = f2tf32(v);
    *ph = __uint_as_float(h);
    uint32_t l = f2tf32(v - __uint_as_float(h));
    *pl = __uint_as_float(l);
}

__device__ __forceinline__ void mma_tf32(float c[4],
    uint32_t a0, uint32_t a1, uint32_t a2, uint32_t a3,
    uint32_t b0, uint32_t b1)
{
    asm volatile(
        "mma.sync.aligned.m16n8k8.row.col.f32.tf32.tf32.f32 "
        "{%0,%1,%2,%3}, {%4,%5,%6,%7}, {%8,%9}, {%0,%1,%2,%3};"
        : "+f"(c[0]), "+f"(c[1]), "+f"(c[2]), "+f"(c[3])
        : "r"(a0), "r"(a1), "r"(a2), "r"(a3), "r"(b0), "r"(b1));
}

__device__ __forceinline__ void cp_async16(float* smem, const float* gmem) {
    uint32_t s;
    asm("{ .reg .u64 t; cvta.to.shared.u64 t, %1; cvt.u32.u64 %0, t; }"
        : "=r"(s) : "l"(smem));
    asm volatile("cp.async.cg.shared.global [%0], [%1], 16;" :: "r"(s), "l"(gmem) : "memory");
}
#define CP_COMMIT()  asm volatile("cp.async.commit_group;" ::: "memory")
#define CP_WAIT1()   asm volatile("cp.async.wait_group 1;" ::: "memory")
#define CP_WAIT0()   asm volatile("cp.async.wait_group 0;" ::: "memory")

// ---------------- fused embed + init + first rmsnorm (cur = start) ----------------
__global__ void embednorm_k(const int* __restrict__ ids, const int* __restrict__ start,
                            const float* __restrict__ emb, const float* __restrict__ n1,
                            float* __restrict__ x,
                            float* __restrict__ outh, float* __restrict__ outl) {
    int t = blockIdx.x;
    int d = threadIdx.x;          // 512
    __shared__ float red[512];
    if (t == 0 && d == 0) {
        g_cur[0] = start[0];
        g_cur[1] = start[1];
        #pragma unroll
        for (int i = 0; i < Cc+1; i++) g_accp[i] = 0.f;
        g_acclb = 0.f;
    }
    float v = emb[(size_t)ids[t]*Dd + d] * sqrtf((float)Dd);
    x[t*Dd + d] = v;
    red[d] = v*v;
    __syncthreads();
    for (int s = 256; s > 0; s >>= 1) {
        if (d < s) red[d] += red[d+s];
        __syncthreads();
    }
    float scale = rsqrtf(red[0] * (1.0f/Dd) + 1e-6f);
    float o = v * scale * n1[(size_t)start[t / Ss] * Dd + d];
    split_store(o, &outh[t*Dd + d], &outl[t*Dd + d]);
}

// ---------------- rmsnorm (block per token), hi/lo output ----------------
__global__ void rmsnorm_k(const float* __restrict__ x, const float* __restrict__ w,
                          const int* __restrict__ cur,
                          float* __restrict__ outh, float* __restrict__ outl) {
    int t = blockIdx.x;
    int d = threadIdx.x;          // 512
    __shared__ float red[512];
    float v = x[t*Dd + d];
    red[d] = v*v;
    __syncthreads();
    for (int s = 256; s > 0; s >>= 1) {
        if (d < s) red[d] += red[d+s];
        __syncthreads();
    }
    float scale = rsqrtf(red[0] * (1.0f/Dd) + 1e-6f);
    const float* ww = w;
    if (cur) ww += (size_t)cur[t / Ss] * Dd;
    float o = v * scale * ww[d];
    split_store(o, &outh[t*Dd + d], &outl[t*Dd + d]);
}

// ---------------- tensor-core logits GEMM (A pre-converted to tf32 hi) ------
#define TC_SMEM ((2*128*36 + 2*32*136) * (int)sizeof(float))
__global__ void __launch_bounds__(256,2) gemm_tc(
    const float* __restrict__ A, const float* __restrict__ W,
    float* __restrict__ Out, int K, int N, int aux_n)
{
    extern __shared__ float dsm[];
    float (*As)[128][36]  = (float(*)[128][36])dsm;
    float (*Bs)[32][136]  = (float(*)[32][136])(dsm + 2*128*36);
    int tid = threadIdx.x;
    int m0 = blockIdx.x*128, n0 = blockIdx.y*128;
    int warp = tid >> 5, lane = tid & 31;
    int wm = warp & 1, wn = warp >> 1;
    int g = lane >> 2, tg = lane & 3;

    if (blockIdx.x == 0 && blockIdx.y == 0 && tid == 0 && aux_n > 0) {
        float avg[Cc+1];
        float m = 0.f;
        #pragma unroll
        for (int i = 0; i < Cc+1; i++) { avg[i] = g_accp[i] * 0.25f; m += avg[i]; }
        m *= 1.f/(Cc+1);
        float var = 0.f;
        #pragma unroll
        for (int i = 0; i < Cc+1; i++) { float d = avg[i] - m; var += d*d; }
        var *= 1.f/(Cc+1);
        Out[aux_n-2] = var;
        Out[aux_n-1] = g_acclb * 0.5f;
    }

    auto issue = [&](int k0, int buf) {
        #pragma unroll
        for (int l = 0; l < 4; l++) {
            int idx = tid + l*256;
            int row = idx >> 3, kc = (idx & 7) * 4;
            cp_async16(&As[buf][row][kc], &A[(size_t)(m0+row)*K + k0 + kc]);
        }
        #pragma unroll
        for (int l = 0; l < 4; l++) {
            int idx = tid + l*256;
            int kr = idx >> 5, nc = (idx & 31) * 4;
            cp_async16(&Bs[buf][kr][nc], &W[(size_t)(k0+kr)*N + n0 + nc]);
        }
        CP_COMMIT();
    };

    float acc[4][4][4] = {};
    int nk = K / 32;
    issue(0, 0);
    int buf = 0;
    for (int it = 0; it < nk; it++) {
        bool more = (it + 1) < nk;
        if (more) issue((it+1)*32, buf^1);
        if (more) CP_WAIT1(); else CP_WAIT0();
        __syncthreads();

        #pragma unroll
        for (int kk = 0; kk < 32; kk += 8) {
            uint32_t af[4][4], bf[4][2];
            #pragma unroll
            for (int mt = 0; mt < 4; mt++) {
                int mrow = wm*64 + mt*16 + g;
                af[mt][0] = __float_as_uint(As[buf][mrow  ][kk+tg]);
                af[mt][1] = __float_as_uint(As[buf][mrow+8][kk+tg]);
                af[mt][2] = __float_as_uint(As[buf][mrow  ][kk+tg+4]);
                af[mt][3] = __float_as_uint(As[buf][mrow+8][kk+tg+4]);
            }
            #pragma unroll
            for (int nt = 0; nt < 4; nt++) {
                int ncol = wn*32 + nt*8 + g;
                bf[nt][0] = f2tf32(Bs[buf][kk+tg  ][ncol]);
                bf[nt][1] = f2tf32(Bs[buf][kk+tg+4][ncol]);
            }
            #pragma unroll
            for (int mt = 0; mt < 4; mt++)
                #pragma unroll
                for (int nt = 0; nt < 4; nt++)
                    mma_tf32(acc[mt][nt], af[mt][0], af[mt][1], af[mt][2], af[mt][3],
                             bf[nt][0], bf[nt][1]);
        }
        __syncthreads();
        buf ^= 1;
    }

    #pragma unroll
    for (int mt = 0; mt < 4; mt++) {
        #pragma unroll
        for (int nt = 0; nt < 4; nt++) {
            int row = m0 + wm*64 + mt*16 + g;
            int col = n0 + wn*32 + nt*8 + 2*tg;
            float2 lo = { acc[mt][nt][0], acc[mt][nt][1] };
            float2 hi = { acc[mt][nt][2], acc[mt][nt][3] };
            *(float2*)&Out[(size_t)row*N + col]     = lo;
            *(float2*)&Out[(size_t)(row+8)*N + col] = hi;
        }
    }
}

// ---------------- tf32x3 mid GEMM core, A pre-split (dynamic smem) ----------------
// smem layout: AsH[2][64][36], AsL[2][64][36], Bs[2][32][72]  = 13824 floats
#define TC64_SMEM (13824 * (int)sizeof(float))
__device__ __forceinline__ void tc64_core(
    const float* __restrict__ Ah, const float* __restrict__ Al, int lda,
    const float* __restrict__ W,
    int K, int N, int m0, int n0, int tid, float acc[2][2][4], float* sm)
{
    float (*AsH)[64][36] = (float(*)[64][36])sm;
    float (*AsL)[64][36] = (float(*)[64][36])(sm + 2*64*36);
    float (*Bs)[32][72]  = (float(*)[32][72])(sm + 4*64*36);
    int warp = tid >> 5, lane = tid & 31;
    int wm = warp & 1, wn = warp >> 1;
    int g = lane >> 2, tg = lane & 3;

    auto issue = [&](int k0, int buf) {
        #pragma unroll
        for (int l = 0; l < 2; l++) {
            int idx = tid + l*256;
            int row = idx >> 3, kc = (idx & 7) * 4;
            size_t goff = (size_t)(m0+row)*lda + k0 + kc;
            cp_async16(&AsH[buf][row][kc], &Ah[goff]);
            cp_async16(&AsL[buf][row][kc], &Al[goff]);
        }
        #pragma unroll
        for (int l = 0; l < 2; l++) {
            int idx = tid + l*256;
            int kr = idx >> 4, nc = (idx & 15) * 4;
            cp_async16(&Bs[buf][kr][nc], &W[(size_t)(k0+kr)*N + n0 + nc]);
        }
        CP_COMMIT();
    };

    int nk = K / 32;
    issue(0, 0);
    int buf = 0;
    for (int it = 0; it < nk; it++) {
        bool more = (it + 1) < nk;
        if (more) issue((it+1)*32, buf^1);
        if (more) CP_WAIT1(); else CP_WAIT0();
        __syncthreads();

        #pragma unroll
        for (int kk = 0; kk < 32; kk += 8) {
            uint32_t ah[2][4], al[2][4], bh[2][2], bl[2][2];
            #pragma unroll
            for (int mt = 0; mt < 2; mt++) {
                int mrow = wm*32 + mt*16 + g;
                ah[mt][0] = __float_as_uint(AsH[buf][mrow  ][kk+tg]);
                ah[mt][1] = __float_as_uint(AsH[buf][mrow+8][kk+tg]);
                ah[mt][2] = __float_as_uint(AsH[buf][mrow  ][kk+tg+4]);
                ah[mt][3] = __float_as_uint(AsH[buf][mrow+8][kk+tg+4]);
                al[mt][0] = __float_as_uint(AsL[buf][mrow  ][kk+tg]);
                al[mt][1] = __float_as_uint(AsL[buf][mrow+8][kk+tg]);
                al[mt][2] = __float_as_uint(AsL[buf][mrow  ][kk+tg+4]);
                al[mt][3] = __float_as_uint(AsL[buf][mrow+8][kk+tg+4]);
            }
            #pragma unroll
            for (int nt = 0; nt < 2; nt++) {
                int ncol = wn*16 + nt*8 + g;
                float b0 = Bs[buf][kk+tg  ][ncol];
                float b1 = Bs[buf][kk+tg+4][ncol];
                bh[nt][0] = f2tf32(b0); bl[nt][0] = f2tf32(b0 - __uint_as_float(bh[nt][0]));
                bh[nt][1] = f2tf32(b1); bl[nt][1] = f2tf32(b1 - __uint_as_float(bh[nt][1]));
            }
            #pragma unroll
            for (int mt = 0; mt < 2; mt++)
                #pragma unroll
                for (int nt = 0; nt < 2; nt++) {
                    mma_tf32(acc[mt][nt], ah[mt][0], ah[mt][1], ah[mt][2], ah[mt][3],
                             bl[nt][0], bl[nt][1]);
                    mma_tf32(acc[mt][nt], al[mt][0], al[mt][1], al[mt][2], al[mt][3],
                             bh[nt][0], bh[nt][1]);
                    mma_tf32(acc[mt][nt], ah[mt][0], ah[mt][1], ah[mt][2], ah[mt][3],
                             bh[nt][0], bh[nt][1]);
                }
        }
        __syncthreads();
        buf ^= 1;
    }
}

// shared epilogue. epi: 0 store, 1 res+acc, 2 silu, 3 silu+split-store(Out=hi, Out2=lo)
__device__ __forceinline__ void tc64_epilogue(
    float acc[2][2][4], const float* __restrict__ res,
    float* __restrict__ Out, float* __restrict__ Out2,
    int N, int m0, int n0, int tid, int epi)
{
    int warp = tid >> 5, lane = tid & 31;
    int wm = warp & 1, wn = warp >> 1;
    int g = lane >> 2, tg = lane & 3;
    #pragma unroll
    for (int mt = 0; mt < 2; mt++) {
        #pragma unroll
        for (int nt = 0; nt < 2; nt++) {
            int row = m0 + wm*32 + mt*16 + g;
            int col = n0 + wn*16 + nt*8 + 2*tg;
            float2 lo = { acc[mt][nt][0], acc[mt][nt][1] };
            float2 hi = { acc[mt][nt][2], acc[mt][nt][3] };
            if (epi == 1) {
                float2 r0 = *(const float2*)&res[(size_t)row*N + col];
                float2 r1 = *(const float2*)&res[(size_t)(row+8)*N + col];
                lo.x += r0.x; lo.y += r0.y;
                hi.x += r1.x; hi.y += r1.y;
            } else if (epi >= 2) {
                lo.x = lo.x / (1.f + expf(-lo.x));
                lo.y = lo.y / (1.f + expf(-lo.y));
                hi.x = hi.x / (1.f + expf(-hi.x));
                hi.y = hi.y / (1.f + expf(-hi.y));
            }
            if (epi == 3) {
                size_t r0i = (size_t)row*N + col, r1i = (size_t)(row+8)*N + col;
                float2 loh, lol, hih, hil;
                uint32_t u;
                u = f2tf32(lo.x); loh.x = __uint_as_float(u); lol.x = __uint_as_float(f2tf32(lo.x - loh.x));
                u = f2tf32(lo.y); loh.y = __uint_as_float(u); lol.y = __uint_as_float(f2tf32(lo.y - loh.y));
                u = f2tf32(hi.x); hih.x = __uint_as_float(u); hil.x = __uint_as_float(f2tf32(hi.x - hih.x));
                u = f2tf32(hi.y); hih.y = __uint_as_float(u); hil.y = __uint_as_float(f2tf32(hi.y - hih.y));
                *(float2*)&Out [r0i] = loh; *(float2*)&Out2[r0i] = lol;
                *(float2*)&Out [r1i] = hih; *(float2*)&Out2[r1i] = hil;
            } else {
                *(float2*)&Out[(size_t)row*N + col]     = lo;
                *(float2*)&Out[(size_t)(row+8)*N + col] = hi;
            }
        }
    }
}

// ---------------- mid GEMM, direct (used for W1: epi=3 silu+split) ----------------
__global__ void __launch_bounds__(256) gemm_mid_tc(
    const float* __restrict__ Ah, const float* __restrict__ Al,
    const float* __restrict__ Wb,
    const float* __restrict__ res, float* __restrict__ Out, float* __restrict__ Out2,
    const int* __restrict__ cur, int K, int N, int epi)
{
    extern __shared__ float sm[];
    int m0 = blockIdx.y*64, n0 = blockIdx.x*64;
    const float* W = Wb;
    if (cur) W += (size_t)cur[m0 / Ss] * K * N;
    float acc[2][2][4] = {};
    tc64_core(Ah, Al, K, W, K, N, m0, n0, threadIdx.x, acc, sm);
    tc64_epilogue(acc, res, Out, Out2, N, m0, n0, threadIdx.x, epi);
}

// ---------------- split-K mid GEMM -> partials (N = Dd) ----------------
__global__ void __launch_bounds__(256) gemm_sk(
    const float* __restrict__ Ah, const float* __restrict__ Al, int lda,
    const float* __restrict__ Wb,
    float* __restrict__ part, const int* __restrict__ cur, int Kfull, int klen)
{
    extern __shared__ float sm[];
    int m0 = blockIdx.y*64, n0 = blockIdx.x*64;
    int z = blockIdx.z;
    const float* W = Wb + (size_t)cur[m0 / Ss] * Kfull * Dd + (size_t)z * klen * Dd;
    float acc[2][2][4] = {};
    tc64_core(Ah + (size_t)z * klen, Al + (size_t)z * klen, lda, W, klen, Dd,
              m0, n0, threadIdx.x, acc, sm);
    tc64_epilogue(acc, nullptr, part + (size_t)z * TOK * Dd, nullptr, Dd, m0, n0, threadIdx.x, 0);
}

// ---------------- split-K QKV -> 6 partials ----------------
__global__ void __launch_bounds__(256) qkv_sk(
    const float* __restrict__ xnh, const float* __restrict__ xnl,
    const float* __restrict__ Wq, const float* __restrict__ Wk, const float* __restrict__ Wv,
    float* __restrict__ part, const int* __restrict__ cur)
{
    extern __shared__ float sm[];
    int z = blockIdx.z;
    int op = z >> 1, half = z & 1;
    const float* Wb = (op == 0) ? Wq : (op == 1) ? Wk : Wv;
    int m0 = blockIdx.y*64, n0 = blockIdx.x*64;
    const float* W = Wb + (size_t)cur[m0 / Ss] * Dd * Dd + (size_t)half * 256 * Dd;
    float acc[2][2][4] = {};
    tc64_core(xnh + (size_t)half * 256, xnl + (size_t)half * 256, Dd, W, 256, Dd,
              m0, n0, threadIdx.x, acc, sm);
    tc64_epilogue(acc, nullptr, part + (size_t)z * TOK * Dd, nullptr, Dd, m0, n0, threadIdx.x, 0);
}

// ---------------- fused qkv reduce (2 partials each) + rope ----------------
__global__ void qkvrope_k(const float* __restrict__ part,
                          float* __restrict__ q, float* __restrict__ k, float* __restrict__ v) {
    int t = blockIdx.x;
    int s = t % Ss;
    int i = threadIdx.x;
    int base = t*Dd + 2*i;
    float q0=0, q1=0, k0=0, k1=0, v0=0, v1=0;
    #pragma unroll
    for (int z = 0; z < 2; z++) {
        const float* pq = part + (size_t)z      * TOK*Dd + base;
        const float* pk = part + (size_t)(2+z)  * TOK*Dd + base;
        const float* pv = part + (size_t)(4+z)  * TOK*Dd + base;
        q0 += pq[0]; q1 += pq[1];
        k0 += pk[0]; k1 += pk[1];
        v0 += pv[0]; v1 += pv[1];
    }
    int j = i & 31;
    float inv = powf(10000.f, -(2.f*j) / 64.f);
    float ang = (float)s * inv;
    float c = cosf(ang), sn = sinf(ang);
    q[base]   = q0*c - q1*sn;
    q[base+1] = q0*sn + q1*c;
    k[base]   = k0*c - k1*sn;
    k[base+1] = k0*sn + k1*c;
    v[base]   = v0;
    v[base+1] = v1;
}

// ---------------- fused Wo reduce (2 partials) + residual + rmsnorm(n2) ------
__global__ void rednorm_k(float* __restrict__ x, const float* __restrict__ part,
                          const float* __restrict__ w, const int* __restrict__ cur,
                          float* __restrict__ outh, float* __restrict__ outl) {
    int t = blockIdx.x;
    int d = threadIdx.x;          // 512
    __shared__ float red[512];
    int idx = t*Dd + d;
    float v = x[idx];
    #pragma unroll
    for (int z = 0; z < 2; z++) v += part[(size_t)z*TOK*Dd + idx];
    x[idx] = v;
    red[d] = v*v;
    __syncthreads();
    for (int s = 256; s > 0; s >>= 1) {
        if (d < s) red[d] += red[d+s];
        __syncthreads();
    }
    float scale = rsqrtf(red[0] * (1.0f/Dd) + 1e-6f);
    float o = v * scale * w[(size_t)cur[t / Ss] * Dd + d];
    split_store(o, &outh[idx], &outl[idx]);
}

// ---------------- reduce: x += sum of S partials ----------------
__global__ void red_add(float* __restrict__ x, const float* __restrict__ part, int S) {
    int i = blockIdx.x*256 + threadIdx.x;
    float s = x[i];
    for (int j = 0; j < S; j++) s += part[(size_t)j*TOK*Dd + i];
    x[i] = s;
}

// ---------------- flash attention v2 (verified R11), hi/lo O output ----------------
#define ATT_SMEM ((32*68 + 64*68 + 64*68 + 32*68) * (int)sizeof(float))
__global__ void __launch_bounds__(256,2) fattn_k(
    const float* __restrict__ q, const float* __restrict__ k,
    const float* __restrict__ v,
    float* __restrict__ oh, float* __restrict__ ol)
{
    extern __shared__ float asm_[];
    float (*Qs)[68] = (float(*)[68])asm_;
    float (*Ks)[68] = (float(*)[68])(asm_ + 32*68);
    float (*Vs)[68] = (float(*)[68])(asm_ + 32*68 + 64*68);
    float (*Ps)[68] = (float(*)[68])(asm_ + 32*68 + 2*64*68);
    int qt = blockIdx.x, h = blockIdx.y, b = blockIdx.z;
    int tid = threadIdx.x;
    int row = tid >> 3;
    int sub = tid & 7;
    int base_bh = b*Ss*Dd + h*HD;
    int gq = qt*32 + row;

    #pragma unroll
    for (int l = 0; l < 2; l++) {
        int idx = tid + l*256;
        int r = idx >> 4;
        int c = (idx & 15) * 4;
        *(float4*)&Qs[r][c] = *(const float4*)&q[base_bh + (qt*32 + r)*Dd + c];
    }

    float m = -1e30f, lsum = 0.f;
    float Oacc[8];
    #pragma unroll
    for (int t = 0; t < 8; t++) Oacc[t] = 0.f;

    int nkt = qt/2 + 1;
    for (int kt = 0; kt < nkt; kt++) {
        __syncthreads();
        #pragma unroll
        for (int l = 0; l < 4; l++) {
            int idx = tid + l*256;
            int r = idx >> 4;
            int c = (idx & 15) * 4;
            *(float4*)&Ks[r][c] = *(const float4*)&k[base_bh + (kt*64 + r)*Dd + c];
            *(float4*)&Vs[r][c] = *(const float4*)&v[base_bh + (kt*64 + r)*Dd + c];
        }
        __syncthreads();

        float s[8];
        #pragma unroll
        for (int jj = 0; jj < 8; jj++) s[jj] = 0.f;
        for (int d = 0; d < HD; d++) {
            float qd = Qs[row][d];
            #pragma unroll
            for (int jj = 0; jj < 8; jj++)
                s[jj] = fmaf(qd, Ks[sub + jj*8][d], s[jj]);
        }
        int kbase = kt*64;
        float mt_ = -1e30f;
        #pragma unroll
        for (int jj = 0; jj < 8; jj++) {
            int jg = kbase + sub + jj*8;
            s[jj] = (jg <= gq) ? s[jj]*0.125f : -1e30f;
            mt_ = fmaxf(mt_, s[jj]);
        }
        mt_ = fmaxf(mt_, __shfl_xor_sync(0xffffffffu, mt_, 1));
        mt_ = fmaxf(mt_, __shfl_xor_sync(0xffffffffu, mt_, 2));
        mt_ = fmaxf(mt_, __shfl_xor_sync(0xffffffffu, mt_, 4));
        float m_new = fmaxf(m, mt_);
        float factor = expf(m - m_new);
        float lt = 0.f;
        #pragma unroll
        for (int jj = 0; jj < 8; jj++) {
            float p = expf(s[jj] - m_new);
            Ps[row][sub + jj*8] = p;
            lt += p;
        }
        lt += __shfl_xor_sync(0xffffffffu, lt, 1);
        lt += __shfl_xor_sync(0xffffffffu, lt, 2);
        lt += __shfl_xor_sync(0xffffffffu, lt, 4);
        lsum = lsum * factor + lt;
        m = m_new;
        #pragma unroll
        for (int t = 0; t < 8; t++) Oacc[t] *= factor;
        __syncwarp();

        for (int j = 0; j < 64; j++) {
            float pj = Ps[row][j];
            #pragma unroll
            for (int t = 0; t < 8; t++)
                Oacc[t] = fmaf(pj, Vs[j][sub + 8*t], Oacc[t]);
        }
    }

    float inv = 1.f / lsum;
    #pragma unroll
    for (int t = 0; t < 8; t++) {
        float vo = Oacc[t] * inv;
        size_t idx = base_bh + (size_t)gq*Dd + sub + 8*t;
        split_store(vo, &oh[idx], &ol[idx]);
    }
}

// ---------------- parallel pooling ----------------
__global__ void pool_k(const float* __restrict__ x, float* __restrict__ pooled) {
    int b = blockIdx.y;
    int d = blockIdx.x*128 + threadIdx.x;
    float s = 0.f;
    #pragma unroll 4
    for (int ss = 0; ss < Ss; ss++) s += x[(size_t)(b*Ss+ss)*Dd + d];
    pooled[b*Dd + d] = s * (1.f/Ss);
}

// ---------------- gating + routing (single block, reads pooled) ----------------
__global__ void gate_k(const float* __restrict__ pooled, const float* __restrict__ gw) {
    __shared__ float red[512];
    __shared__ float sc[2*(Cc+1)];
    int tid = threadIdx.x;
    for (int idx = 0; idx < 2*(Cc+1); idx++) {
        int b = idx / (Cc+1), c = idx % (Cc+1);
        red[tid] = pooled[b*Dd + tid] * gw[tid*(Cc+1) + c];
        __syncthreads();
        for (int s = 256; s > 0; s >>= 1) {
            if (tid < s) red[tid] += red[tid+s];
            __syncthreads();
        }
        if (tid == 0) sc[idx] = red[0];
        __syncthreads();
    }
    if (tid == 0) {
        float p[Bb][Cc+1];
        for (int b = 0; b < Bb; b++) {
            float mx = -1e30f;
            for (int c = 0; c < Cc+1; c++) mx = fmaxf(mx, sc[b*(Cc+1)+c]);
            float sum = 0.f;
            for (int c = 0; c < Cc+1; c++) { p[b][c] = expf(sc[b*(Cc+1)+c] - mx); sum += p[b][c]; }
            for (int c = 0; c < Cc+1; c++) p[b][c] /= sum;
        }
        float lb = 0.f;
        for (int c = 0; c < Cc+1; c++) {
            g_accp[c] += p[0][c] + p[1][c];
            float avg = 0.5f * (p[0][c] + p[1][c]);
            lb += avg*avg;
        }
        g_acclb += (float)(Cc+1) * lb;
        for (int b = 0; b < Bb; b++) {
            int co = g_cur[b];
            int j1 = (co+1) & 3, j2 = (co+2) & 3;
            float s1 = sc[b*(Cc+1)+j1], s2 = sc[b*(Cc+1)+j2];
            int w;
            if (s1 > s2) w = j1;
            else if (s2 > s1) w = j2;
            else w = (j1 < j2) ? j1 : j2;
            g_cur[b] = w;
        }
    }
}

// ---------------- host orchestration ----------------
extern "C" void kernel_launch(void* const* d_in, const int* in_sizes, int n_in,
                              void* d_out, int out_size) {
    const int*   ids   = (const int*)  d_in[0];
    const int*   start = (const int*)  d_in[1];
    const float* emb   = (const float*)d_in[2];
    const float* Wq    = (const float*)d_in[3];
    const float* Wk    = (const float*)d_in[4];
    const float* Wv    = (const float*)d_in[5];
    const float* Wo    = (const float*)d_in[6];
    const float* W1    = (const float*)d_in[7];
    const float* W2    = (const float*)d_in[8];
    const float* n1    = (const float*)d_in[9];
    const float* n2    = (const float*)d_in[10];
    const float* gw    = (const float*)d_in[11];
    const float* fnw   = (const float*)d_in[12];
    const float* fcw   = (const float*)d_in[13];
    float* out = (float*)d_out;

    float *x, *xnh, *xnl, *q, *k, *v, *oh, *ol, *ffh, *ffl, *part, *pool;
    int* cur;
    cudaGetSymbolAddress((void**)&x,   g_x);
    cudaGetSymbolAddress((void**)&xnh, g_xnh);
    cudaGetSymbolAddress((void**)&xnl, g_xnl);
    cudaGetSymbolAddress((void**)&q,   g_q);
    cudaGetSymbolAddress((void**)&k,   g_k);
    cudaGetSymbolAddress((void**)&v,   g_v);
    cudaGetSymbolAddress((void**)&oh,  g_oh);
    cudaGetSymbolAddress((void**)&ol,  g_ol);
    cudaGetSymbolAddress((void**)&ffh, g_ffh);
    cudaGetSymbolAddress((void**)&ffl, g_ffl);
    cudaGetSymbolAddress((void**)&part, g_part);
    cudaGetSymbolAddress((void**)&pool, g_pool);
    cudaGetSymbolAddress((void**)&cur, g_cur);

    static int smem_set = 0;
    if (!smem_set) {
        cudaFuncSetAttribute(gemm_tc,    cudaFuncAttributeMaxDynamicSharedMemorySize, TC_SMEM);
        cudaFuncSetAttribute(fattn_k,    cudaFuncAttributeMaxDynamicSharedMemorySize, ATT_SMEM);
        cudaFuncSetAttribute(qkv_sk,     cudaFuncAttributeMaxDynamicSharedMemorySize, TC64_SMEM);
        cudaFuncSetAttribute(gemm_sk,    cudaFuncAttributeMaxDynamicSharedMemorySize, TC64_SMEM);
        cudaFuncSetAttribute(gemm_mid_tc,cudaFuncAttributeMaxDynamicSharedMemorySize, TC64_SMEM);
        smem_set = 1;
    }

    embednorm_k<<<TOK, Dd>>>(ids, start, emb, n1, x, xnh, xnl);

    int nred = TOK*Dd/256;            // 1024 blocks
    dim3 gqkv(Dd/64, TOK/64, 6);      // 384 blocks (split-K=2 x q,k,v)
    dim3 gwo (Dd/64, TOK/64, 2);      // 128 blocks (split-K=2)
    dim3 gw1 (Ff/64, TOK/64);         // 256 blocks
    dim3 gw2 (Dd/64, TOK/64, 4);      // 256 blocks (split-K=4)
    dim3 gatt(Ss/32, Hh, Bb);         // 128 blocks
    for (int step = 0; step < 2; step++) {
        if (step > 0)
            rmsnorm_k<<<TOK, Dd>>>(x, n1, cur, xnh, xnl);
        qkv_sk<<<gqkv, 256, TC64_SMEM>>>(xnh, xnl, Wq, Wk, Wv, part, cur);
        qkvrope_k<<<TOK, 256>>>(part, q, k, v);
        fattn_k<<<gatt, 256, ATT_SMEM>>>(q, k, v, oh, ol);
        gemm_sk<<<gwo, 256, TC64_SMEM>>>(oh, ol, Dd, Wo, part, cur, Dd, 256);
        rednorm_k<<<TOK, Dd>>>(x, part, n2, cur, xnh, xnl);
        gemm_mid_tc<<<gw1, 256, TC64_SMEM>>>(xnh, xnl, W1, nullptr, ffh, ffl, cur, Dd, Ff, 3);
        gemm_sk<<<gw2, 256, TC64_SMEM>>>(ffh, ffl, Ff, W2, part, cur, Ff, 512);
        red_add<<<nred, 256>>>(x, part, 4);
        pool_k<<<dim3(Dd/128, Bb), 128>>>(x, pool);
        gate_k<<<1, 512>>>(pool, gw);
    }
    rmsnorm_k<<<TOK, Dd>>>(x, fnw, nullptr, xnh, xnl);
    gemm_tc<<<dim3(TOK/128, Vv/128), 256, TC_SMEM>>>(xnh, fcw, out, Dd, Vv, out_size);
}

// round 13
// speedup vs baseline: 2.8509x; 1.0090x over previous
#include <cuda_runtime.h>
#include <math.h>
#include <stdint.h>

#define Dd  512
#define Hh  8
#define HD  64
#define Bb  2
#define Ss  256
#define Ff  2048
#define Cc  4
#define Vv  32000
#define TOK (Bb*Ss)   // 512

// ---------------- device state (no allocation allowed) ----------------
__device__ float g_x  [TOK*Dd];
__device__ float g_xnh[TOK*Dd];
__device__ float g_xnl[TOK*Dd];
__device__ float g_q  [TOK*Dd];
__device__ float g_k  [TOK*Dd];
__device__ float g_v  [TOK*Dd];
__device__ float g_oh [TOK*Dd];
__device__ float g_ol [TOK*Dd];
__device__ float g_ffh[TOK*Ff];
__device__ float g_ffl[TOK*Ff];
__device__ float g_part[6*TOK*Dd];
__device__ float g_pool[Bb*Dd];
__device__ int   g_cur[Bb];
__device__ float g_accp[Cc+1];
__device__ float g_acclb;

// ---------------- tf32 / cp.async helpers ----------------
__device__ __forceinline__ uint32_t f2tf32(float f) {
    uint32_t u;
    asm volatile("cvt.rna.tf32.f32 %0, %1;" : "=r"(u) : "f"(f));
    return u;
}

__device__ __forceinline__ void split_store(float v, float* __restrict__ ph, float* __restrict__ pl) {
    uint32_t h = f2tf32(v);
    *ph = __uint_as_float(h);
    uint32_t l = f2tf32(v - __uint_as_float(h));
    *pl = __uint_as_float(l);
}

__device__ __forceinline__ void mma_tf32(float c[4],
    uint32_t a0, uint32_t a1, uint32_t a2, uint32_t a3,
    uint32_t b0, uint32_t b1)
{
    asm volatile(
        "mma.sync.aligned.m16n8k8.row.col.f32.tf32.tf32.f32 "
        "{%0,%1,%2,%3}, {%4,%5,%6,%7}, {%8,%9}, {%0,%1,%2,%3};"
        : "+f"(c[0]), "+f"(c[1]), "+f"(c[2]), "+f"(c[3])
        : "r"(a0), "r"(a1), "r"(a2), "r"(a3), "r"(b0), "r"(b1));
}

__device__ __forceinline__ void cp_async16(float* smem, const float* gmem) {
    uint32_t s;
    asm("{ .reg .u64 t; cvta.to.shared.u64 t, %1; cvt.u32.u64 %0, t; }"
        : "=r"(s) : "l"(smem));
    asm volatile("cp.async.cg.shared.global [%0], [%1], 16;" :: "r"(s), "l"(gmem) : "memory");
}
#define CP_COMMIT()  asm volatile("cp.async.commit_group;" ::: "memory")
#define CP_WAIT1()   asm volatile("cp.async.wait_group 1;" ::: "memory")
#define CP_WAIT0()   asm volatile("cp.async.wait_group 0;" ::: "memory")

// ---------------- fused embed + init + first rmsnorm (cur = start) ----------------
__global__ void embednorm_k(const int* __restrict__ ids, const int* __restrict__ start,
                            const float* __restrict__ emb, const float* __restrict__ n1,
                            float* __restrict__ x,
                            float* __restrict__ outh, float* __restrict__ outl) {
    int t = blockIdx.x;
    int d = threadIdx.x;          // 512
    __shared__ float red[512];
    if (t == 0 && d == 0) {
        g_cur[0] = start[0];
        g_cur[1] = start[1];
        #pragma unroll
        for (int i = 0; i < Cc+1; i++) g_accp[i] = 0.f;
        g_acclb = 0.f;
    }
    float v = emb[(size_t)ids[t]*Dd + d] * sqrtf((float)Dd);
    x[t*Dd + d] = v;
    red[d] = v*v;
    __syncthreads();
    for (int s = 256; s > 0; s >>= 1) {
        if (d < s) red[d] += red[d+s];
        __syncthreads();
    }
    float scale = rsqrtf(red[0] * (1.0f/Dd) + 1e-6f);
    float o = v * scale * n1[(size_t)start[t / Ss] * Dd + d];
    split_store(o, &outh[t*Dd + d], &outl[t*Dd + d]);
}

// ---------------- rmsnorm (block per token), hi/lo output ----------------
__global__ void rmsnorm_k(const float* __restrict__ x, const float* __restrict__ w,
                          const int* __restrict__ cur,
                          float* __restrict__ outh, float* __restrict__ outl) {
    int t = blockIdx.x;
    int d = threadIdx.x;          // 512
    __shared__ float red[512];
    float v = x[t*Dd + d];
    red[d] = v*v;
    __syncthreads();
    for (int s = 256; s > 0; s >>= 1) {
        if (d < s) red[d] += red[d+s];
        __syncthreads();
    }
    float scale = rsqrtf(red[0] * (1.0f/Dd) + 1e-6f);
    const float* ww = w;
    if (cur) ww += (size_t)cur[t / Ss] * Dd;
    float o = v * scale * ww[d];
    split_store(o, &outh[t*Dd + d], &outl[t*Dd + d]);
}

// ---------------- tensor-core logits GEMM (A pre-converted to tf32 hi) ------
#define TC_SMEM ((2*128*36 + 2*32*136) * (int)sizeof(float))
__global__ void __launch_bounds__(256,2) gemm_tc(
    const float* __restrict__ A, const float* __restrict__ W,
    float* __restrict__ Out, int K, int N, int aux_n)
{
    extern __shared__ float dsm[];
    float (*As)[128][36]  = (float(*)[128][36])dsm;
    float (*Bs)[32][136]  = (float(*)[32][136])(dsm + 2*128*36);
    int tid = threadIdx.x;
    int m0 = blockIdx.x*128, n0 = blockIdx.y*128;
    int warp = tid >> 5, lane = tid & 31;
    int wm = warp & 1, wn = warp >> 1;
    int g = lane >> 2, tg = lane & 3;

    if (blockIdx.x == 0 && blockIdx.y == 0 && tid == 0 && aux_n > 0) {
        float avg[Cc+1];
        float m = 0.f;
        #pragma unroll
        for (int i = 0; i < Cc+1; i++) { avg[i] = g_accp[i] * 0.25f; m += avg[i]; }
        m *= 1.f/(Cc+1);
        float var = 0.f;
        #pragma unroll
        for (int i = 0; i < Cc+1; i++) { float d = avg[i] - m; var += d*d; }
        var *= 1.f/(Cc+1);
        Out[aux_n-2] = var;
        Out[aux_n-1] = g_acclb * 0.5f;
    }

    auto issue = [&](int k0, int buf) {
        #pragma unroll
        for (int l = 0; l < 4; l++) {
            int idx = tid + l*256;
            int row = idx >> 3, kc = (idx & 7) * 4;
            cp_async16(&As[buf][row][kc], &A[(size_t)(m0+row)*K + k0 + kc]);
        }
        #pragma unroll
        for (int l = 0; l < 4; l++) {
            int idx = tid + l*256;
            int kr = idx >> 5, nc = (idx & 31) * 4;
            cp_async16(&Bs[buf][kr][nc], &W[(size_t)(k0+kr)*N + n0 + nc]);
        }
        CP_COMMIT();
    };

    float acc[4][4][4] = {};
    int nk = K / 32;
    issue(0, 0);
    int buf = 0;
    for (int it = 0; it < nk; it++) {
        bool more = (it + 1) < nk;
        if (more) issue((it+1)*32, buf^1);
        if (more) CP_WAIT1(); else CP_WAIT0();
        __syncthreads();

        #pragma unroll
        for (int kk = 0; kk < 32; kk += 8) {
            uint32_t af[4][4], bf[4][2];
            #pragma unroll
            for (int mt = 0; mt < 4; mt++) {
                int mrow = wm*64 + mt*16 + g;
                af[mt][0] = __float_as_uint(As[buf][mrow  ][kk+tg]);
                af[mt][1] = __float_as_uint(As[buf][mrow+8][kk+tg]);
                af[mt][2] = __float_as_uint(As[buf][mrow  ][kk+tg+4]);
                af[mt][3] = __float_as_uint(As[buf][mrow+8][kk+tg+4]);
            }
            #pragma unroll
            for (int nt = 0; nt < 4; nt++) {
                int ncol = wn*32 + nt*8 + g;
                bf[nt][0] = f2tf32(Bs[buf][kk+tg  ][ncol]);
                bf[nt][1] = f2tf32(Bs[buf][kk+tg+4][ncol]);
            }
            #pragma unroll
            for (int mt = 0; mt < 4; mt++)
                #pragma unroll
                for (int nt = 0; nt < 4; nt++)
                    mma_tf32(acc[mt][nt], af[mt][0], af[mt][1], af[mt][2], af[mt][3],
                             bf[nt][0], bf[nt][1]);
        }
        __syncthreads();
        buf ^= 1;
    }

    #pragma unroll
    for (int mt = 0; mt < 4; mt++) {
        #pragma unroll
        for (int nt = 0; nt < 4; nt++) {
            int row = m0 + wm*64 + mt*16 + g;
            int col = n0 + wn*32 + nt*8 + 2*tg;
            float2 lo = { acc[mt][nt][0], acc[mt][nt][1] };
            float2 hi = { acc[mt][nt][2], acc[mt][nt][3] };
            *(float2*)&Out[(size_t)row*N + col]     = lo;
            *(float2*)&Out[(size_t)(row+8)*N + col] = hi;
        }
    }
}

// ---------------- tf32x3 mid GEMM core, A pre-split, 3 independent acc banks ----
// smem layout: AsH[2][64][36], AsL[2][64][36], Bs[2][32][72]  = 13824 floats
#define TC64_SMEM (13824 * (int)sizeof(float))
__device__ __forceinline__ void tc64_core(
    const float* __restrict__ Ah, const float* __restrict__ Al, int lda,
    const float* __restrict__ W,
    int K, int N, int m0, int n0, int tid, float acc[2][2][4], float* sm)
{
    float (*AsH)[64][36] = (float(*)[64][36])sm;
    float (*AsL)[64][36] = (float(*)[64][36])(sm + 2*64*36);
    float (*Bs)[32][72]  = (float(*)[32][72])(sm + 4*64*36);
    int warp = tid >> 5, lane = tid & 31;
    int wm = warp & 1, wn = warp >> 1;
    int g = lane >> 2, tg = lane & 3;

    auto issue = [&](int k0, int buf) {
        #pragma unroll
        for (int l = 0; l < 2; l++) {
            int idx = tid + l*256;
            int row = idx >> 3, kc = (idx & 7) * 4;
            size_t goff = (size_t)(m0+row)*lda + k0 + kc;
            cp_async16(&AsH[buf][row][kc], &Ah[goff]);
            cp_async16(&AsL[buf][row][kc], &Al[goff]);
        }
        #pragma unroll
        for (int l = 0; l < 2; l++) {
            int idx = tid + l*256;
            int kr = idx >> 4, nc = (idx & 15) * 4;
            cp_async16(&Bs[buf][kr][nc], &W[(size_t)(k0+kr)*N + n0 + nc]);
        }
        CP_COMMIT();
    };

    // 3 independent accumulator banks: [0]=ah*bl, [1]=al*bh, [2]=ah*bh
    float a3[3][2][2][4] = {};

    int nk = K / 32;
    issue(0, 0);
    int buf = 0;
    for (int it = 0; it < nk; it++) {
        bool more = (it + 1) < nk;
        if (more) issue((it+1)*32, buf^1);
        if (more) CP_WAIT1(); else CP_WAIT0();
        __syncthreads();

        #pragma unroll
        for (int kk = 0; kk < 32; kk += 8) {
            uint32_t ah[2][4], al[2][4], bh[2][2], bl[2][2];
            #pragma unroll
            for (int mt = 0; mt < 2; mt++) {
                int mrow = wm*32 + mt*16 + g;
                ah[mt][0] = __float_as_uint(AsH[buf][mrow  ][kk+tg]);
                ah[mt][1] = __float_as_uint(AsH[buf][mrow+8][kk+tg]);
                ah[mt][2] = __float_as_uint(AsH[buf][mrow  ][kk+tg+4]);
                ah[mt][3] = __float_as_uint(AsH[buf][mrow+8][kk+tg+4]);
                al[mt][0] = __float_as_uint(AsL[buf][mrow  ][kk+tg]);
                al[mt][1] = __float_as_uint(AsL[buf][mrow+8][kk+tg]);
                al[mt][2] = __float_as_uint(AsL[buf][mrow  ][kk+tg+4]);
                al[mt][3] = __float_as_uint(AsL[buf][mrow+8][kk+tg+4]);
            }
            #pragma unroll
            for (int nt = 0; nt < 2; nt++) {
                int ncol = wn*16 + nt*8 + g;
                float b0 = Bs[buf][kk+tg  ][ncol];
                float b1 = Bs[buf][kk+tg+4][ncol];
                bh[nt][0] = f2tf32(b0); bl[nt][0] = f2tf32(b0 - __uint_as_float(bh[nt][0]));
                bh[nt][1] = f2tf32(b1); bl[nt][1] = f2tf32(b1 - __uint_as_float(bh[nt][1]));
            }
            // 12 MMAs, all to distinct accumulators -> independent chains
            #pragma unroll
            for (int mt = 0; mt < 2; mt++)
                #pragma unroll
                for (int nt = 0; nt < 2; nt++) {
                    mma_tf32(a3[0][mt][nt], ah[mt][0], ah[mt][1], ah[mt][2], ah[mt][3],
                             bl[nt][0], bl[nt][1]);
                    mma_tf32(a3[1][mt][nt], al[mt][0], al[mt][1], al[mt][2], al[mt][3],
                             bh[nt][0], bh[nt][1]);
                    mma_tf32(a3[2][mt][nt], ah[mt][0], ah[mt][1], ah[mt][2], ah[mt][3],
                             bh[nt][0], bh[nt][1]);
                }
        }
        __syncthreads();
        buf ^= 1;
    }

    #pragma unroll
    for (int mt = 0; mt < 2; mt++)
        #pragma unroll
        for (int nt = 0; nt < 2; nt++)
            #pragma unroll
            for (int c = 0; c < 4; c++)
                acc[mt][nt][c] = a3[2][mt][nt][c] + (a3[0][mt][nt][c] + a3[1][mt][nt][c]);
}

// shared epilogue. epi: 0 store, 1 res+acc, 2 silu, 3 silu+split-store(Out=hi, Out2=lo)
__device__ __forceinline__ void tc64_epilogue(
    float acc[2][2][4], const float* __restrict__ res,
    float* __restrict__ Out, float* __restrict__ Out2,
    int N, int m0, int n0, int tid, int epi)
{
    int warp = tid >> 5, lane = tid & 31;
    int wm = warp & 1, wn = warp >> 1;
    int g = lane >> 2, tg = lane & 3;
    #pragma unroll
    for (int mt = 0; mt < 2; mt++) {
        #pragma unroll
        for (int nt = 0; nt < 2; nt++) {
            int row = m0 + wm*32 + mt*16 + g;
            int col = n0 + wn*16 + nt*8 + 2*tg;
            float2 lo = { acc[mt][nt][0], acc[mt][nt][1] };
            float2 hi = { acc[mt][nt][2], acc[mt][nt][3] };
            if (epi == 1) {
                float2 r0 = *(const float2*)&res[(size_t)row*N + col];
                float2 r1 = *(const float2*)&res[(size_t)(row+8)*N + col];
                lo.x += r0.x; lo.y += r0.y;
                hi.x += r1.x; hi.y += r1.y;
            } else if (epi >= 2) {
                lo.x = lo.x / (1.f + expf(-lo.x));
                lo.y = lo.y / (1.f + expf(-lo.y));
                hi.x = hi.x / (1.f + expf(-hi.x));
                hi.y = hi.y / (1.f + expf(-hi.y));
            }
            if (epi == 3) {
                size_t r0i = (size_t)row*N + col, r1i = (size_t)(row+8)*N + col;
                float2 loh, lol, hih, hil;
                uint32_t u;
                u = f2tf32(lo.x); loh.x = __uint_as_float(u); lol.x = __uint_as_float(f2tf32(lo.x - loh.x));
                u = f2tf32(lo.y); loh.y = __uint_as_float(u); lol.y = __uint_as_float(f2tf32(lo.y - loh.y));
                u = f2tf32(hi.x); hih.x = __uint_as_float(u); hil.x = __uint_as_float(f2tf32(hi.x - hih.x));
                u = f2tf32(hi.y); hih.y = __uint_as_float(u); hil.y = __uint_as_float(f2tf32(hi.y - hih.y));
                *(float2*)&Out [r0i] = loh; *(float2*)&Out2[r0i] = lol;
                *(float2*)&Out [r1i] = hih; *(float2*)&Out2[r1i] = hil;
            } else {
                *(float2*)&Out[(size_t)row*N + col]     = lo;
                *(float2*)&Out[(size_t)(row+8)*N + col] = hi;
            }
        }
    }
}

// ---------------- mid GEMM, direct (used for W1: epi=3 silu+split) ----------------
__global__ void __launch_bounds__(256) gemm_mid_tc(
    const float* __restrict__ Ah, const float* __restrict__ Al,
    const float* __restrict__ Wb,
    const float* __restrict__ res, float* __restrict__ Out, float* __restrict__ Out2,
    const int* __restrict__ cur, int K, int N, int epi)
{
    extern __shared__ float sm[];
    int m0 = blockIdx.y*64, n0 = blockIdx.x*64;
    const float* W = Wb;
    if (cur) W += (size_t)cur[m0 / Ss] * K * N;
    float acc[2][2][4] = {};
    tc64_core(Ah, Al, K, W, K, N, m0, n0, threadIdx.x, acc, sm);
    tc64_epilogue(acc, res, Out, Out2, N, m0, n0, threadIdx.x, epi);
}

// ---------------- split-K mid GEMM -> partials (N = Dd) ----------------
__global__ void __launch_bounds__(256) gemm_sk(
    const float* __restrict__ Ah, const float* __restrict__ Al, int lda,
    const float* __restrict__ Wb,
    float* __restrict__ part, const int* __restrict__ cur, int Kfull, int klen)
{
    extern __shared__ float sm[];
    int m0 = blockIdx.y*64, n0 = blockIdx.x*64;
    int z = blockIdx.z;
    const float* W = Wb + (size_t)cur[m0 / Ss] * Kfull * Dd + (size_t)z * klen * Dd;
    float acc[2][2][4] = {};
    tc64_core(Ah + (size_t)z * klen, Al + (size_t)z * klen, lda, W, klen, Dd,
              m0, n0, threadIdx.x, acc, sm);
    tc64_epilogue(acc, nullptr, part + (size_t)z * TOK * Dd, nullptr, Dd, m0, n0, threadIdx.x, 0);
}

// ---------------- split-K QKV -> 6 partials ----------------
__global__ void __launch_bounds__(256) qkv_sk(
    const float* __restrict__ xnh, const float* __restrict__ xnl,
    const float* __restrict__ Wq, const float* __restrict__ Wk, const float* __restrict__ Wv,
    float* __restrict__ part, const int* __restrict__ cur)
{
    extern __shared__ float sm[];
    int z = blockIdx.z;
    int op = z >> 1, half = z & 1;
    const float* Wb = (op == 0) ? Wq : (op == 1) ? Wk : Wv;
    int m0 = blockIdx.y*64, n0 = blockIdx.x*64;
    const float* W = Wb + (size_t)cur[m0 / Ss] * Dd * Dd + (size_t)half * 256 * Dd;
    float acc[2][2][4] = {};
    tc64_core(xnh + (size_t)half * 256, xnl + (size_t)half * 256, Dd, W, 256, Dd,
              m0, n0, threadIdx.x, acc, sm);
    tc64_epilogue(acc, nullptr, part + (size_t)z * TOK * Dd, nullptr, Dd, m0, n0, threadIdx.x, 0);
}

// ---------------- fused qkv reduce (2 partials each) + rope ----------------
__global__ void qkvrope_k(const float* __restrict__ part,
                          float* __restrict__ q, float* __restrict__ k, float* __restrict__ v) {
    int t = blockIdx.x;
    int s = t % Ss;
    int i = threadIdx.x;
    int base = t*Dd + 2*i;
    float q0=0, q1=0, k0=0, k1=0, v0=0, v1=0;
    #pragma unroll
    for (int z = 0; z < 2; z++) {
        const float* pq = part + (size_t)z      * TOK*Dd + base;
        const float* pk = part + (size_t)(2+z)  * TOK*Dd + base;
        const float* pv = part + (size_t)(4+z)  * TOK*Dd + base;
        q0 += pq[0]; q1 += pq[1];
        k0 += pk[0]; k1 += pk[1];
        v0 += pv[0]; v1 += pv[1];
    }
    int j = i & 31;
    float inv = powf(10000.f, -(2.f*j) / 64.f);
    float ang = (float)s * inv;
    float c = cosf(ang), sn = sinf(ang);
    q[base]   = q0*c - q1*sn;
    q[base+1] = q0*sn + q1*c;
    k[base]   = k0*c - k1*sn;
    k[base+1] = k0*sn + k1*c;
    v[base]   = v0;
    v[base+1] = v1;
}

// ---------------- fused Wo reduce (2 partials) + residual + rmsnorm(n2) ------
__global__ void rednorm_k(float* __restrict__ x, const float* __restrict__ part,
                          const float* __restrict__ w, const int* __restrict__ cur,
                          float* __restrict__ outh, float* __restrict__ outl) {
    int t = blockIdx.x;
    int d = threadIdx.x;          // 512
    __shared__ float red[512];
    int idx = t*Dd + d;
    float v = x[idx];
    #pragma unroll
    for (int z = 0; z < 2; z++) v += part[(size_t)z*TOK*Dd + idx];
    x[idx] = v;
    red[d] = v*v;
    __syncthreads();
    for (int s = 256; s > 0; s >>= 1) {
        if (d < s) red[d] += red[d+s];
        __syncthreads();
    }
    float scale = rsqrtf(red[0] * (1.0f/Dd) + 1e-6f);
    float o = v * scale * w[(size_t)cur[t / Ss] * Dd + d];
    split_store(o, &outh[idx], &outl[idx]);
}

// ---------------- reduce: x += sum of S partials ----------------
__global__ void red_add(float* __restrict__ x, const float* __restrict__ part, int S) {
    int i = blockIdx.x*256 + threadIdx.x;
    float s = x[i];
    for (int j = 0; j < S; j++) s += part[(size_t)j*TOK*Dd + i];
    x[i] = s;
}

// ---------------- flash attention v2 (verified R11), hi/lo O output ----------------
#define ATT_SMEM ((32*68 + 64*68 + 64*68 + 32*68) * (int)sizeof(float))
__global__ void __launch_bounds__(256,2) fattn_k(
    const float* __restrict__ q, const float* __restrict__ k,
    const float* __restrict__ v,
    float* __restrict__ oh, float* __restrict__ ol)
{
    extern __shared__ float asm_[];
    float (*Qs)[68] = (float(*)[68])asm_;
    float (*Ks)[68] = (float(*)[68])(asm_ + 32*68);
    float (*Vs)[68] = (float(*)[68])(asm_ + 32*68 + 64*68);
    float (*Ps)[68] = (float(*)[68])(asm_ + 32*68 + 2*64*68);
    int qt = blockIdx.x, h = blockIdx.y, b = blockIdx.z;
    int tid = threadIdx.x;
    int row = tid >> 3;
    int sub = tid & 7;
    int base_bh = b*Ss*Dd + h*HD;
    int gq = qt*32 + row;

    #pragma unroll
    for (int l = 0; l < 2; l++) {
        int idx = tid + l*256;
        int r = idx >> 4;
        int c = (idx & 15) * 4;
        *(float4*)&Qs[r][c] = *(const float4*)&q[base_bh + (qt*32 + r)*Dd + c];
    }

    float m = -1e30f, lsum = 0.f;
    float Oacc[8];
    #pragma unroll
    for (int t = 0; t < 8; t++) Oacc[t] = 0.f;

    int nkt = qt/2 + 1;
    for (int kt = 0; kt < nkt; kt++) {
        __syncthreads();
        #pragma unroll
        for (int l = 0; l < 4; l++) {
            int idx = tid + l*256;
            int r = idx >> 4;
            int c = (idx & 15) * 4;
            *(float4*)&Ks[r][c] = *(const float4*)&k[base_bh + (kt*64 + r)*Dd + c];
            *(float4*)&Vs[r][c] = *(const float4*)&v[base_bh + (kt*64 + r)*Dd + c];
        }
        __syncthreads();

        float s[8];
        #pragma unroll
        for (int jj = 0; jj < 8; jj++) s[jj] = 0.f;
        for (int d = 0; d < HD; d++) {
            float qd = Qs[row][d];
            #pragma unroll
            for (int jj = 0; jj < 8; jj++)
                s[jj] = fmaf(qd, Ks[sub + jj*8][d], s[jj]);
        }
        int kbase = kt*64;
        float mt_ = -1e30f;
        #pragma unroll
        for (int jj = 0; jj < 8; jj++) {
            int jg = kbase + sub + jj*8;
            s[jj] = (jg <= gq) ? s[jj]*0.125f : -1e30f;
            mt_ = fmaxf(mt_, s[jj]);
        }
        mt_ = fmaxf(mt_, __shfl_xor_sync(0xffffffffu, mt_, 1));
        mt_ = fmaxf(mt_, __shfl_xor_sync(0xffffffffu, mt_, 2));
        mt_ = fmaxf(mt_, __shfl_xor_sync(0xffffffffu, mt_, 4));
        float m_new = fmaxf(m, mt_);
        float factor = expf(m - m_new);
        float lt = 0.f;
        #pragma unroll
        for (int jj = 0; jj < 8; jj++) {
            float p = expf(s[jj] - m_new);
            Ps[row][sub + jj*8] = p;
            lt += p;
        }
        lt += __shfl_xor_sync(0xffffffffu, lt, 1);
        lt += __shfl_xor_sync(0xffffffffu, lt, 2);
        lt += __shfl_xor_sync(0xffffffffu, lt, 4);
        lsum = lsum * factor + lt;
        m = m_new;
        #pragma unroll
        for (int t = 0; t < 8; t++) Oacc[t] *= factor;
        __syncwarp();

        for (int j = 0; j < 64; j++) {
            float pj = Ps[row][j];
            #pragma unroll
            for (int t = 0; t < 8; t++)
                Oacc[t] = fmaf(pj, Vs[j][sub + 8*t], Oacc[t]);
        }
    }

    float inv = 1.f / lsum;
    #pragma unroll
    for (int t = 0; t < 8; t++) {
        float vo = Oacc[t] * inv;
        size_t idx = base_bh + (size_t)gq*Dd + sub + 8*t;
        split_store(vo, &oh[idx], &ol[idx]);
    }
}

// ---------------- parallel pooling ----------------
__global__ void pool_k(const float* __restrict__ x, float* __restrict__ pooled) {
    int b = blockIdx.y;
    int d = blockIdx.x*128 + threadIdx.x;
    float s = 0.f;
    #pragma unroll 4
    for (int ss = 0; ss < Ss; ss++) s += x[(size_t)(b*Ss+ss)*Dd + d];
    pooled[b*Dd + d] = s * (1.f/Ss);
}

// ---------------- gating + routing (single block, reads pooled) ----------------
__global__ void gate_k(const float* __restrict__ pooled, const float* __restrict__ gw) {
    __shared__ float red[512];
    __shared__ float sc[2*(Cc+1)];
    int tid = threadIdx.x;
    for (int idx = 0; idx < 2*(Cc+1); idx++) {
        int b = idx / (Cc+1), c = idx % (Cc+1);
        red[tid] = pooled[b*Dd + tid] * gw[tid*(Cc+1) + c];
        __syncthreads();
        for (int s = 256; s > 0; s >>= 1) {
            if (tid < s) red[tid] += red[tid+s];
            __syncthreads();
        }
        if (tid == 0) sc[idx] = red[0];
        __syncthreads();
    }
    if (tid == 0) {
        float p[Bb][Cc+1];
        for (int b = 0; b < Bb; b++) {
            float mx = -1e30f;
            for (int c = 0; c < Cc+1; c++) mx = fmaxf(mx, sc[b*(Cc+1)+c]);
            float sum = 0.f;
            for (int c = 0; c < Cc+1; c++) { p[b][c] = expf(sc[b*(Cc+1)+c] - mx); sum += p[b][c]; }
            for (int c = 0; c < Cc+1; c++) p[b][c] /= sum;
        }
        float lb = 0.f;
        for (int c = 0; c < Cc+1; c++) {
            g_accp[c] += p[0][c] + p[1][c];
            float avg = 0.5f * (p[0][c] + p[1][c]);
            lb += avg*avg;
        }
        g_acclb += (float)(Cc+1) * lb;
        for (int b = 0; b < Bb; b++) {
            int co = g_cur[b];
            int j1 = (co+1) & 3, j2 = (co+2) & 3;
            float s1 = sc[b*(Cc+1)+j1], s2 = sc[b*(Cc+1)+j2];
            int w;
            if (s1 > s2) w = j1;
            else if (s2 > s1) w = j2;
            else w = (j1 < j2) ? j1 : j2;
            g_cur[b] = w;
        }
    }
}

// ---------------- host orchestration ----------------
extern "C" void kernel_launch(void* const* d_in, const int* in_sizes, int n_in,
                              void* d_out, int out_size) {
    const int*   ids   = (const int*)  d_in[0];
    const int*   start = (const int*)  d_in[1];
    const float* emb   = (const float*)d_in[2];
    const float* Wq    = (const float*)d_in[3];
    const float* Wk    = (const float*)d_in[4];
    const float* Wv    = (const float*)d_in[5];
    const float* Wo    = (const float*)d_in[6];
    const float* W1    = (const float*)d_in[7];
    const float* W2    = (const float*)d_in[8];
    const float* n1    = (const float*)d_in[9];
    const float* n2    = (const float*)d_in[10];
    const float* gw    = (const float*)d_in[11];
    const float* fnw   = (const float*)d_in[12];
    const float* fcw   = (const float*)d_in[13];
    float* out = (float*)d_out;

    float *x, *xnh, *xnl, *q, *k, *v, *oh, *ol, *ffh, *ffl, *part, *pool;
    int* cur;
    cudaGetSymbolAddress((void**)&x,   g_x);
    cudaGetSymbolAddress((void**)&xnh, g_xnh);
    cudaGetSymbolAddress((void**)&xnl, g_xnl);
    cudaGetSymbolAddress((void**)&q,   g_q);
    cudaGetSymbolAddress((void**)&k,   g_k);
    cudaGetSymbolAddress((void**)&v,   g_v);
    cudaGetSymbolAddress((void**)&oh,  g_oh);
    cudaGetSymbolAddress((void**)&ol,  g_ol);
    cudaGetSymbolAddress((void**)&ffh, g_ffh);
    cudaGetSymbolAddress((void**)&ffl, g_ffl);
    cudaGetSymbolAddress((void**)&part, g_part);
    cudaGetSymbolAddress((void**)&pool, g_pool);
    cudaGetSymbolAddress((void**)&cur, g_cur);

    static int smem_set = 0;
    if (!smem_set) {
        cudaFuncSetAttribute(gemm_tc,    cudaFuncAttributeMaxDynamicSharedMemorySize, TC_SMEM);
        cudaFuncSetAttribute(fattn_k,    cudaFuncAttributeMaxDynamicSharedMemorySize, ATT_SMEM);
        cudaFuncSetAttribute(qkv_sk,     cudaFuncAttributeMaxDynamicSharedMemorySize, TC64_SMEM);
        cudaFuncSetAttribute(gemm_sk,    cudaFuncAttributeMaxDynamicSharedMemorySize, TC64_SMEM);
        cudaFuncSetAttribute(gemm_mid_tc,cudaFuncAttributeMaxDynamicSharedMemorySize, TC64_SMEM);
        smem_set = 1;
    }

    embednorm_k<<<TOK, Dd>>>(ids, start, emb, n1, x, xnh, xnl);

    int nred = TOK*Dd/256;            // 1024 blocks
    dim3 gqkv(Dd/64, TOK/64, 6);      // 384 blocks (split-K=2 x q,k,v)
    dim3 gwo (Dd/64, TOK/64, 2);      // 128 blocks (split-K=2)
    dim3 gw1 (Ff/64, TOK/64);         // 256 blocks
    dim3 gw2 (Dd/64, TOK/64, 4);      // 256 blocks (split-K=4)
    dim3 gatt(Ss/32, Hh, Bb);         // 128 blocks
    for (int step = 0; step < 2; step++) {
        if (step > 0)
            rmsnorm_k<<<TOK, Dd>>>(x, n1, cur, xnh, xnl);
        qkv_sk<<<gqkv, 256, TC64_SMEM>>>(xnh, xnl, Wq, Wk, Wv, part, cur);
        qkvrope_k<<<TOK, 256>>>(part, q, k, v);
        fattn_k<<<gatt, 256, ATT_SMEM>>>(q, k, v, oh, ol);
        gemm_sk<<<gwo, 256, TC64_SMEM>>>(oh, ol, Dd, Wo, part, cur, Dd, 256);
        rednorm_k<<<TOK, Dd>>>(x, part, n2, cur, xnh, xnl);
        gemm_mid_tc<<<gw1, 256, TC64_SMEM>>>(xnh, xnl, W1, nullptr, ffh, ffl, cur, Dd, Ff, 3);
        gemm_sk<<<gw2, 256, TC64_SMEM>>>(ffh, ffl, Ff, W2, part, cur, Ff, 512);
        red_add<<<nred, 256>>>(x, part, 4);
        pool_k<<<dim3(Dd/128, Bb), 128>>>(x, pool);
        gate_k<<<1, 512>>>(pool, gw);
    }
    rmsnorm_k<<<TOK, Dd>>>(x, fnw, nullptr, xnh, xnl);
    gemm_tc<<<dim3(TOK/128, Vv/128), 256, TC_SMEM>>>(xnh, fcw, out, Dd, Vv, out_size);
}